// round 1
// baseline (speedup 1.0000x reference)
#include <cuda_runtime.h>
#include <math.h>

#define KSEL 2000
#define HH 75
#define WW 100
#define HWSZ 7500
#define NB 8
#define CH 512
#define ND 128
#define NSORT 8192

// ---------------- scratch (static device allocations) ----------------
__device__ int   g_sorted_idx[NB * KSEL];
__device__ int   g_pos[NB * HWSZ];
__device__ float g_nf[(size_t)NB * KSEL * CH];   // clipped gathered features
__device__ float g_g1[NB * KSEL * ND];           // nf @ w1
__device__ float g_x1[NB * KSEL * ND];           // A@g1 + b1
__device__ float g_g2[NB * KSEL * ND];           // x1 @ w2

// ---------------- kernel 1: per-batch top-K + sort + pos map ----------------
extern "C" __global__ __launch_bounds__(1024)
void topk_kernel(const float* __restrict__ predict, float* __restrict__ out, int write_idx) {
    extern __shared__ unsigned long long keys[];   // NSORT entries (64KB)
    __shared__ int sidx[2048];
    const int b = blockIdx.x;
    const int tid = threadIdx.x;
    const float* sc = predict + (size_t)b * 3 * HWSZ;   // channel 0 scores

    // init inverse map
    for (int i = tid; i < HWSZ; i += 1024) g_pos[b * HWSZ + i] = -1;

    // pack keys: high 32 = descending score order, low 32 = index (ascending tiebreak)
    for (int i = tid; i < NSORT; i += 1024) {
        unsigned long long kk;
        if (i < HWSZ) {
            unsigned u = __float_as_uint(sc[i]);
            unsigned ord = (u & 0x80000000u) ? ~u : (u ^ 0x80000000u); // monotone ascending
            unsigned desc = ~ord;                                      // monotone descending
            kk = (((unsigned long long)desc) << 32) | (unsigned)i;
        } else {
            kk = 0xFFFFFFFFFFFFFFFFULL;  // pad sorts last
        }
        keys[i] = kk;
    }
    __syncthreads();

    // bitonic sort (ascending) of 8192 keys
    for (int size = 2; size <= NSORT; size <<= 1) {
        for (int stride = size >> 1; stride > 0; stride >>= 1) {
            for (int i = tid; i < NSORT; i += 1024) {
                int j = i ^ stride;
                if (j > i) {
                    unsigned long long a = keys[i], c = keys[j];
                    bool up = ((i & size) == 0);
                    if ((a > c) == up) { keys[i] = c; keys[j] = a; }
                }
            }
            __syncthreads();
        }
    }

    // take first 2000 indices, sort ascending
    for (int i = tid; i < 2048; i += 1024)
        sidx[i] = (i < KSEL) ? (int)(keys[i] & 0xFFFFFFFFu) : 0x7FFFFFFF;
    __syncthreads();
    for (int size = 2; size <= 2048; size <<= 1) {
        for (int stride = size >> 1; stride > 0; stride >>= 1) {
            for (int i = tid; i < 2048; i += 1024) {
                int j = i ^ stride;
                if (j > i) {
                    int a = sidx[i], c = sidx[j];
                    bool up = ((i & size) == 0);
                    if ((a > c) == up) { sidx[i] = c; sidx[j] = a; }
                }
            }
            __syncthreads();
        }
    }

    for (int k = tid; k < KSEL; k += 1024) {
        int i = sidx[k];
        g_sorted_idx[b * KSEL + k] = i;
        g_pos[b * HWSZ + i] = k;
        if (write_idx) out[(size_t)NB * KSEL * ND + b * KSEL + k] = (float)i;
    }
}

// ---------------- kernel 2: gather + clip node features ----------------
// block (k, b) of 128 threads; nf[b][k][c] = clip(F[b, c, i%75, i/75], 0, 6)
extern "C" __global__ __launch_bounds__(128)
void gather_kernel(const float* __restrict__ feat) {
    const int b = blockIdx.y, k = blockIdx.x, tid = threadIdx.x;
    const int i = g_sorted_idx[b * KSEL + k];
    const int y = i % HH, x = i / HH;
    const float* fb = feat + (size_t)b * CH * HWSZ + y * WW + x;
    float* dst = g_nf + (size_t)(b * KSEL + k) * CH;
    #pragma unroll
    for (int c = tid; c < CH; c += 128) {
        float v = fb[(size_t)c * HWSZ];
        dst[c] = fminf(fmaxf(v, 0.0f), 6.0f);
    }
}

// ---------------- fp32 SIMT GEMM: C[M][128] = A[M][KD] @ B[KD][128] ----------------
template <int KD>
__device__ __forceinline__ void gemm_body(const float* __restrict__ A,
                                          const float* __restrict__ B,
                                          float* __restrict__ C) {
    __shared__ float As[64][20];    // padded, row-major
    __shared__ float Bs[16][128];
    const int tid = threadIdx.x;                 // 256 threads
    const int tx = tid & 31, ty = tid >> 5;
    const int m0 = ty * 8, n0 = tx * 4;
    const int gm = blockIdx.x * 64;
    const int arow = tid >> 2, akq = (tid & 3) * 4;
    const int brow0 = tid >> 5, bcol0 = (tid & 31) * 4;       // first 8 rows
    float acc[8][4];
    #pragma unroll
    for (int r = 0; r < 8; r++)
        #pragma unroll
        for (int c = 0; c < 4; c++) acc[r][c] = 0.0f;

    for (int k0 = 0; k0 < KD; k0 += 16) {
        float4 av  = *(const float4*)&A[(size_t)(gm + arow) * KD + k0 + akq];
        float4 bv0 = *(const float4*)&B[(k0 + brow0) * ND + bcol0];
        float4 bv1 = *(const float4*)&B[(k0 + brow0 + 8) * ND + bcol0];
        __syncthreads();   // previous compute done
        As[arow][akq + 0] = av.x; As[arow][akq + 1] = av.y;
        As[arow][akq + 2] = av.z; As[arow][akq + 3] = av.w;
        *(float4*)&Bs[brow0][bcol0]     = bv0;
        *(float4*)&Bs[brow0 + 8][bcol0] = bv1;
        __syncthreads();
        #pragma unroll
        for (int kk = 0; kk < 16; kk++) {
            float4 bv = *(const float4*)&Bs[kk][n0];
            #pragma unroll
            for (int r = 0; r < 8; r++) {
                float a = As[m0 + r][kk];   // warp-uniform broadcast
                acc[r][0] += a * bv.x; acc[r][1] += a * bv.y;
                acc[r][2] += a * bv.z; acc[r][3] += a * bv.w;
            }
        }
    }
    #pragma unroll
    for (int r = 0; r < 8; r++) {
        float4 o = make_float4(acc[r][0], acc[r][1], acc[r][2], acc[r][3]);
        *(float4*)&C[(size_t)(gm + m0 + r) * ND + n0] = o;
    }
}

extern "C" __global__ __launch_bounds__(256)
void gemm1_kernel(const float* __restrict__ B) { gemm_body<CH>(g_nf, B, g_g1); }

extern "C" __global__ __launch_bounds__(256)
void gemm2_kernel(const float* __restrict__ B) { gemm_body<ND>(g_x1, B, g_g2); }

// ---------------- kernel 4: x1 = A@g1 + b1 (sparse 3x3 neighbor sum) ----------------
extern "C" __global__ __launch_bounds__(128)
void nsum1_kernel(const float* __restrict__ b1) {
    const int b = blockIdx.y, k = blockIdx.x, c = threadIdx.x;
    const int row = b * KSEL + k;
    const int i = g_sorted_idx[row];
    const int py = i / WW, px = i % WW;
    float acc = b1[k * ND + c];
    #pragma unroll
    for (int dy = -1; dy <= 1; dy++) {
        int ny = py + dy;
        if ((unsigned)ny >= HH) continue;
        #pragma unroll
        for (int dx = -1; dx <= 1; dx++) {
            int nx = px + dx;
            if ((unsigned)nx >= WW) continue;
            int n = g_pos[b * HWSZ + ny * WW + nx];
            if (n >= 0) acc += g_g1[(b * KSEL + n) * ND + c];
        }
    }
    g_x1[row * ND + c] = acc;
}

// ---------------- kernel 6: out = tanh(A@g2 + b2 + x1) ----------------
extern "C" __global__ __launch_bounds__(128)
void final_kernel(const float* __restrict__ b2, float* __restrict__ out) {
    const int b = blockIdx.y, k = blockIdx.x, c = threadIdx.x;
    const int row = b * KSEL + k;
    const int i = g_sorted_idx[row];
    const int py = i / WW, px = i % WW;
    float acc = b2[k * ND + c] + g_x1[row * ND + c];
    #pragma unroll
    for (int dy = -1; dy <= 1; dy++) {
        int ny = py + dy;
        if ((unsigned)ny >= HH) continue;
        #pragma unroll
        for (int dx = -1; dx <= 1; dx++) {
            int nx = px + dx;
            if ((unsigned)nx >= WW) continue;
            int n = g_pos[b * HWSZ + ny * WW + nx];
            if (n >= 0) acc += g_g2[(b * KSEL + n) * ND + c];
        }
    }
    out[(size_t)row * ND + c] = tanhf(acc);
}

// ---------------- launch ----------------
extern "C" void kernel_launch(void* const* d_in, const int* in_sizes, int n_in,
                              void* d_out, int out_size) {
    const float* feat = (const float*)d_in[0];   // (8,512,75,100)
    const float* pred = (const float*)d_in[1];   // (8,3,75,100)
    const float* w1   = (const float*)d_in[2];   // (512,128)
    const float* b1   = (const float*)d_in[3];   // (2000,128)
    const float* w2   = (const float*)d_in[4];   // (128,128)
    const float* b2   = (const float*)d_in[5];   // (2000,128)
    float* out = (float*)d_out;

    const int feat_elems = NB * KSEL * ND;            // 2,048,000
    const int write_idx = (out_size >= feat_elems + NB * KSEL) ? 1 : 0;

    cudaFuncSetAttribute((const void*)topk_kernel,
                         cudaFuncAttributeMaxDynamicSharedMemorySize, NSORT * 8);

    topk_kernel<<<NB, 1024, NSORT * 8>>>(pred, out, write_idx);
    gather_kernel<<<dim3(KSEL, NB), 128>>>(feat);
    gemm1_kernel<<<(NB * KSEL) / 64, 256>>>(w1);
    nsum1_kernel<<<dim3(KSEL, NB), 128>>>(b1);
    gemm2_kernel<<<(NB * KSEL) / 64, 256>>>(w2);
    final_kernel<<<dim3(KSEL, NB), 128>>>(b2, out);
}

// round 3
// speedup vs baseline: 1.4988x; 1.4988x over previous
#include <cuda_runtime.h>
#include <math.h>

#define KSEL 2000
#define HH 75
#define WW 100
#define HWSZ 7500
#define NB 8
#define CH 512
#define ND 128
#define NROWS (NB * KSEL)

// ---------------- scratch (static device allocations) ----------------
__device__ int   g_sorted_idx[NROWS];
__device__ int   g_pos[NB * HWSZ];
__device__ float g_nf[(size_t)NROWS * CH];   // clipped gathered features
__device__ float g_g1[NROWS * ND];           // nf @ w1
__device__ float g_x1[NROWS * ND];           // A@g1 + b1
__device__ float g_g2[NROWS * ND];           // x1 @ w2

__device__ __forceinline__ unsigned desckey(float f) {
    unsigned u = __float_as_uint(f);
    unsigned ord = (u & 0x80000000u) ? ~u : (u ^ 0x80000000u); // ascending monotone
    return ~ord;                                               // descending monotone
}

// ---------------- kernel 1: per-batch exact top-K via radix histogram ----------------
extern "C" __global__ __launch_bounds__(1024)
void topk_kernel(const float* __restrict__ predict, float* __restrict__ out, int write_idx) {
    __shared__ int hist[2048];
    __shared__ int partial[64];
    __shared__ unsigned long long cand[2048];
    __shared__ unsigned char flag[HWSZ];
    __shared__ int scanbuf[1024];
    __shared__ int s_bin, s_before, s_cnt;

    const int b = blockIdx.x;
    const int tid = threadIdx.x;
    const float* sc = predict + (size_t)b * 3 * HWSZ;   // channel 0 scores

    for (int i = tid; i < 2048; i += 1024) hist[i] = 0;
    for (int i = tid; i < HWSZ; i += 1024) { flag[i] = 0; g_pos[b * HWSZ + i] = -1; }
    if (tid == 0) s_cnt = 0;
    __syncthreads();

    // pass 1: histogram over 11-bit prefix of descending key
    for (int i = tid; i < HWSZ; i += 1024)
        atomicAdd(&hist[desckey(sc[i]) >> 21], 1);
    __syncthreads();

    // scan: 64 partials of 32 bins
    if (tid < 64) {
        int s = 0;
        #pragma unroll
        for (int j = 0; j < 32; j++) s += hist[tid * 32 + j];
        partial[tid] = s;
    }
    __syncthreads();
    if (tid == 0) {
        int run = 0;
        for (int t = 0; t < 64; t++) { int v = partial[t]; partial[t] = run; run += v; }
    }
    __syncthreads();
    if (tid < 64) {
        int run = partial[tid];
        #pragma unroll
        for (int j = 0; j < 32; j++) { run += hist[tid * 32 + j]; hist[tid * 32 + j] = run; } // inclusive
    }
    __syncthreads();

    // boundary bin: first bin with cum >= K
    for (int bin = tid; bin < 2048; bin += 1024) {
        int c = hist[bin];
        int cb = (bin == 0) ? 0 : hist[bin - 1];
        if (c >= KSEL && cb < KSEL) { s_bin = bin; s_before = cb; }
    }
    __syncthreads();
    const int Bb = s_bin;
    const int r = KSEL - s_before;

    // pass 2: collect boundary-bin candidates (full key for exact tie order)
    for (int i = tid; i < HWSZ; i += 1024) {
        unsigned k = desckey(sc[i]);
        if ((int)(k >> 21) == Bb) {
            int slot = atomicAdd(&s_cnt, 1);
            if (slot < 2048) cand[slot] = (((unsigned long long)k) << 32) | (unsigned)i;
        }
    }
    __syncthreads();
    int cnt = s_cnt; if (cnt > 2048) cnt = 2048;
    for (int i = tid; i < 2048; i += 1024)
        if (i >= cnt) cand[i] = 0xFFFFFFFFFFFFFFFFULL;
    __syncthreads();

    for (int size = 2; size <= 2048; size <<= 1) {
        for (int stride = size >> 1; stride > 0; stride >>= 1) {
            for (int i = tid; i < 2048; i += 1024) {
                int j = i ^ stride;
                if (j > i) {
                    unsigned long long a = cand[i], c = cand[j];
                    bool up = ((i & size) == 0);
                    if ((a > c) == up) { cand[i] = c; cand[j] = a; }
                }
            }
            __syncthreads();
        }
    }
    for (int j = tid; j < r; j += 1024)
        flag[(int)(cand[j] & 0xFFFFFFFFu)] = 1;
    __syncthreads();

    // pass 3: stable in-order compaction (8 contiguous elements/thread)
    const int lo = tid * 8;
    int mycnt = 0;
    #pragma unroll
    for (int q = 0; q < 8; q++) {
        int i = lo + q;
        if (i < HWSZ) {
            int bin = desckey(sc[i]) >> 21;
            if (bin < Bb || flag[i]) mycnt++;
        }
    }
    scanbuf[tid] = mycnt;
    __syncthreads();
    for (int off = 1; off < 1024; off <<= 1) {
        int v = (tid >= off) ? scanbuf[tid - off] : 0;
        __syncthreads();
        scanbuf[tid] += v;
        __syncthreads();
    }
    int pos = scanbuf[tid] - mycnt;
    #pragma unroll
    for (int q = 0; q < 8; q++) {
        int i = lo + q;
        if (i < HWSZ) {
            int bin = desckey(sc[i]) >> 21;
            if (bin < Bb || flag[i]) {
                g_sorted_idx[b * KSEL + pos] = i;
                g_pos[b * HWSZ + i] = pos;
                if (write_idx) out[(size_t)NROWS * ND + b * KSEL + pos] = (float)i;
                pos++;
            }
        }
    }
}

// ---------------- kernel 2: gather + clip node features ----------------
extern "C" __global__ __launch_bounds__(128)
void gather_kernel(const float* __restrict__ feat) {
    const int b = blockIdx.y, k = blockIdx.x, tid = threadIdx.x;
    const int i = g_sorted_idx[b * KSEL + k];
    const int y = i % HH, x = i / HH;
    const float* fb = feat + (size_t)b * CH * HWSZ + y * WW + x;
    float* dst = g_nf + (size_t)(b * KSEL + k) * CH;
    #pragma unroll
    for (int c = tid; c < CH; c += 128) {
        float v = fb[(size_t)c * HWSZ];
        dst[c] = fminf(fmaxf(v, 0.0f), 6.0f);
    }
}

// ---------------- 3xTF32 tensor-core GEMM: C[M][128] = A[M][KD] @ B[KD][128] ----------------
__device__ __forceinline__ unsigned f2tf(float x) {
    unsigned r; asm("cvt.rna.tf32.f32 %0, %1;" : "=r"(r) : "f"(x)); return r;
}

#define MMA_TF32(acc, a0, a1, a2, a3, b0, b1)                                   \
    asm volatile(                                                               \
        "mma.sync.aligned.m16n8k8.row.col.f32.tf32.tf32.f32 "                   \
        "{%0,%1,%2,%3}, {%4,%5,%6,%7}, {%8,%9}, {%0,%1,%2,%3};"                 \
        : "+f"(acc[0]), "+f"(acc[1]), "+f"(acc[2]), "+f"(acc[3])                \
        : "r"(a0), "r"(a1), "r"(a2), "r"(a3), "r"(b0), "r"(b1))

template <int KD>
__device__ __forceinline__ void gemm_tc_body(const float* __restrict__ A,
                                             const float* __restrict__ B,
                                             float* __restrict__ C) {
    __shared__ unsigned AsH[128 * 20];   // [m][k] stride 20
    __shared__ unsigned AsL[128 * 20];
    __shared__ unsigned BsH[16 * 136];   // [k][n] stride 136
    __shared__ unsigned BsL[16 * 136];
    const int tid = threadIdx.x;              // 256 threads = 8 warps
    const int lane = tid & 31;
    const int warp = tid >> 5;
    const int wm = (warp & 3) * 32;           // warp M base
    const int wn = (warp >> 2) * 64;          // warp N base
    const int gm = blockIdx.x * 128;

    float acc[2][8][4];
    #pragma unroll
    for (int mt = 0; mt < 2; mt++)
        #pragma unroll
        for (int nt = 0; nt < 8; nt++)
            #pragma unroll
            for (int q = 0; q < 4; q++) acc[mt][nt][q] = 0.0f;

    for (int k0 = 0; k0 < KD; k0 += 16) {
        // stage global -> regs (A: 128x16 = 512 float4; B: 16x128 = 512 float4)
        float4 av[2], bv[2];
        #pragma unroll
        for (int q = 0; q < 2; q++) {
            int f = tid + 256 * q;
            int row = f >> 2, kc = (f & 3) * 4;
            av[q] = *(const float4*)&A[(size_t)(gm + row) * KD + k0 + kc];
            int br = f >> 5, nc = (f & 31) * 4;
            bv[q] = *(const float4*)&B[(size_t)(k0 + br) * ND + nc];
        }
        __syncthreads();
        #pragma unroll
        for (int q = 0; q < 2; q++) {
            int f = tid + 256 * q;
            int row = f >> 2, kc = (f & 3) * 4;
            float va[4] = {av[q].x, av[q].y, av[q].z, av[q].w};
            #pragma unroll
            for (int e = 0; e < 4; e++) {
                unsigned h = f2tf(va[e]);
                AsH[row * 20 + kc + e] = h;
                AsL[row * 20 + kc + e] = f2tf(va[e] - __uint_as_float(h));
            }
            int br = f >> 5, nc = (f & 31) * 4;
            float vb[4] = {bv[q].x, bv[q].y, bv[q].z, bv[q].w};
            #pragma unroll
            for (int e = 0; e < 4; e++) {
                unsigned h = f2tf(vb[e]);
                BsH[br * 136 + nc + e] = h;
                BsL[br * 136 + nc + e] = f2tf(vb[e] - __uint_as_float(h));
            }
        }
        __syncthreads();

        #pragma unroll
        for (int ks = 0; ks < 2; ks++) {
            const int k8 = ks * 8;
            const int kk = k8 + (lane & 3);
            unsigned aH[2][4], aL[2][4], bH[8][2], bL[8][2];
            #pragma unroll
            for (int mt = 0; mt < 2; mt++) {
                int m0 = wm + mt * 16 + (lane >> 2);
                aH[mt][0] = AsH[m0 * 20 + kk];
                aH[mt][1] = AsH[(m0 + 8) * 20 + kk];
                aH[mt][2] = AsH[m0 * 20 + kk + 4];
                aH[mt][3] = AsH[(m0 + 8) * 20 + kk + 4];
                aL[mt][0] = AsL[m0 * 20 + kk];
                aL[mt][1] = AsL[(m0 + 8) * 20 + kk];
                aL[mt][2] = AsL[m0 * 20 + kk + 4];
                aL[mt][3] = AsL[(m0 + 8) * 20 + kk + 4];
            }
            #pragma unroll
            for (int nt = 0; nt < 8; nt++) {
                int n0 = wn + nt * 8 + (lane >> 2);
                bH[nt][0] = BsH[kk * 136 + n0];
                bH[nt][1] = BsH[(kk + 4) * 136 + n0];
                bL[nt][0] = BsL[kk * 136 + n0];
                bL[nt][1] = BsL[(kk + 4) * 136 + n0];
            }
            #pragma unroll
            for (int mt = 0; mt < 2; mt++)
                #pragma unroll
                for (int nt = 0; nt < 8; nt++) {
                    MMA_TF32(acc[mt][nt], aL[mt][0], aL[mt][1], aL[mt][2], aL[mt][3],
                             bH[nt][0], bH[nt][1]);
                    MMA_TF32(acc[mt][nt], aH[mt][0], aH[mt][1], aH[mt][2], aH[mt][3],
                             bL[nt][0], bL[nt][1]);
                    MMA_TF32(acc[mt][nt], aH[mt][0], aH[mt][1], aH[mt][2], aH[mt][3],
                             bH[nt][0], bH[nt][1]);
                }
        }
        __syncthreads();
    }

    #pragma unroll
    for (int mt = 0; mt < 2; mt++) {
        int row0 = gm + wm + mt * 16 + (lane >> 2);
        int colb = (lane & 3) * 2;
        #pragma unroll
        for (int nt = 0; nt < 8; nt++) {
            int col = wn + nt * 8 + colb;
            *(float2*)&C[(size_t)row0 * ND + col] =
                make_float2(acc[mt][nt][0], acc[mt][nt][1]);
            *(float2*)&C[(size_t)(row0 + 8) * ND + col] =
                make_float2(acc[mt][nt][2], acc[mt][nt][3]);
        }
    }
}

extern "C" __global__ __launch_bounds__(256)
void gemm1_kernel(const float* __restrict__ B) { gemm_tc_body<CH>(g_nf, B, g_g1); }

extern "C" __global__ __launch_bounds__(256)
void gemm2_kernel(const float* __restrict__ B) { gemm_tc_body<ND>(g_x1, B, g_g2); }

// ---------------- sparse 3x3 neighbor sums (warp per row, float4 lanes) ----------------
extern "C" __global__ __launch_bounds__(256)
void nsum1_kernel(const float* __restrict__ b1) {
    const int row = blockIdx.x * 8 + (threadIdx.x >> 5);
    const int lane = threadIdx.x & 31;
    const int b = row / KSEL, k = row - b * KSEL;
    const int i = g_sorted_idx[row];
    const int py = i / WW, px = i % WW;
    int nb = -1;
    if (lane < 9) {
        int ny = py + lane / 3 - 1, nx = px + lane % 3 - 1;
        if ((unsigned)ny < HH && (unsigned)nx < WW)
            nb = g_pos[b * HWSZ + ny * WW + nx];
    }
    float4 acc = *(const float4*)&b1[(size_t)k * ND + lane * 4];
    #pragma unroll
    for (int j = 0; j < 9; j++) {
        int n = __shfl_sync(0xFFFFFFFFu, nb, j);
        if (n >= 0) {
            float4 v = *(const float4*)&g_g1[(size_t)(b * KSEL + n) * ND + lane * 4];
            acc.x += v.x; acc.y += v.y; acc.z += v.z; acc.w += v.w;
        }
    }
    *(float4*)&g_x1[(size_t)row * ND + lane * 4] = acc;
}

extern "C" __global__ __launch_bounds__(256)
void final_kernel(const float* __restrict__ b2, float* __restrict__ out) {
    const int row = blockIdx.x * 8 + (threadIdx.x >> 5);
    const int lane = threadIdx.x & 31;
    const int b = row / KSEL, k = row - b * KSEL;
    const int i = g_sorted_idx[row];
    const int py = i / WW, px = i % WW;
    int nb = -1;
    if (lane < 9) {
        int ny = py + lane / 3 - 1, nx = px + lane % 3 - 1;
        if ((unsigned)ny < HH && (unsigned)nx < WW)
            nb = g_pos[b * HWSZ + ny * WW + nx];
    }
    float4 acc = *(const float4*)&b2[(size_t)k * ND + lane * 4];
    float4 x1v = *(const float4*)&g_x1[(size_t)row * ND + lane * 4];
    acc.x += x1v.x; acc.y += x1v.y; acc.z += x1v.z; acc.w += x1v.w;
    #pragma unroll
    for (int j = 0; j < 9; j++) {
        int n = __shfl_sync(0xFFFFFFFFu, nb, j);
        if (n >= 0) {
            float4 v = *(const float4*)&g_g2[(size_t)(b * KSEL + n) * ND + lane * 4];
            acc.x += v.x; acc.y += v.y; acc.z += v.z; acc.w += v.w;
        }
    }
    float4 o = make_float4(tanhf(acc.x), tanhf(acc.y), tanhf(acc.z), tanhf(acc.w));
    *(float4*)&out[(size_t)row * ND + lane * 4] = o;
}

// ---------------- launch ----------------
extern "C" void kernel_launch(void* const* d_in, const int* in_sizes, int n_in,
                              void* d_out, int out_size) {
    const float* feat = (const float*)d_in[0];   // (8,512,75,100)
    const float* pred = (const float*)d_in[1];   // (8,3,75,100)
    const float* w1   = (const float*)d_in[2];   // (512,128)
    const float* b1   = (const float*)d_in[3];   // (2000,128)
    const float* w2   = (const float*)d_in[4];   // (128,128)
    const float* b2   = (const float*)d_in[5];   // (2000,128)
    float* out = (float*)d_out;

    const int feat_elems = NROWS * ND;            // 2,048,000
    const int write_idx = (out_size >= feat_elems + NROWS) ? 1 : 0;

    topk_kernel<<<NB, 1024>>>(pred, out, write_idx);
    gather_kernel<<<dim3(KSEL, NB), 128>>>(feat);
    gemm1_kernel<<<NROWS / 128, 256>>>(w1);
    nsum1_kernel<<<NROWS / 8, 256>>>(b1);
    gemm2_kernel<<<NROWS / 128, 256>>>(w2);
    final_kernel<<<NROWS / 8, 256>>>(b2, out);
}

// round 4
// speedup vs baseline: 1.9965x; 1.3321x over previous
#include <cuda_runtime.h>
#include <cuda_fp16.h>
#include <math.h>

#define KSEL 2000
#define HH 75
#define WW 100
#define HWSZ 7500
#define NB 8
#define CH 512
#define ND 128
#define NROWS (NB * KSEL)

// ---------------- scratch (static device allocations) ----------------
__device__ int      g_sorted_idx[NROWS];
__device__ int      g_pos[NB * HWSZ];
__device__ float    g_g1[NROWS * ND];           // (A@?) nf @ w1
__device__ float    g_x1[NROWS * ND];           // A@g1 + b1
__device__ float    g_g2[NROWS * ND];           // x1 @ w2
__device__ unsigned g_w1h[ND * (CH / 2)];       // w1 split hi, [n][k2] half2
__device__ unsigned g_w1l[ND * (CH / 2)];
__device__ unsigned g_w2h[ND * (ND / 2)];
__device__ unsigned g_w2l[ND * (ND / 2)];

__device__ __forceinline__ unsigned desckey(float f) {
    unsigned u = __float_as_uint(f);
    unsigned ord = (u & 0x80000000u) ? ~u : (u ^ 0x80000000u);
    return ~ord;
}

__device__ __forceinline__ unsigned pack_split_hi(float v0, float v1) {
    __half h0 = __float2half_rn(v0), h1 = __float2half_rn(v1);
    return (unsigned)__half_as_ushort(h0) | ((unsigned)__half_as_ushort(h1) << 16);
}
__device__ __forceinline__ unsigned pack_split_lo(float v0, float v1) {
    __half h0 = __float2half_rn(v0), h1 = __float2half_rn(v1);
    __half l0 = __float2half_rn(v0 - __half2float(h0));
    __half l1 = __float2half_rn(v1 - __half2float(h1));
    return (unsigned)__half_as_ushort(l0) | ((unsigned)__half_as_ushort(l1) << 16);
}

// ---------------- weight split prep ----------------
extern "C" __global__ __launch_bounds__(256)
void prep_kernel(const float* __restrict__ w1, const float* __restrict__ w2) {
    int idx = blockIdx.x * 256 + threadIdx.x;
    const int N1 = ND * (CH / 2);        // 32768
    if (idx < N1) {
        int f = idx % ND, c2 = idx / ND;
        float v0 = w1[(2 * c2) * ND + f], v1 = w1[(2 * c2 + 1) * ND + f];
        g_w1h[f * (CH / 2) + c2] = pack_split_hi(v0, v1);
        g_w1l[f * (CH / 2) + c2] = pack_split_lo(v0, v1);
    } else {
        int j = idx - N1;                // ND * ND/2 = 8192
        if (j < ND * (ND / 2)) {
            int f = j % ND, c2 = j / ND;
            float v0 = w2[(2 * c2) * ND + f], v1 = w2[(2 * c2 + 1) * ND + f];
            g_w2h[f * (ND / 2) + c2] = pack_split_hi(v0, v1);
            g_w2l[f * (ND / 2) + c2] = pack_split_lo(v0, v1);
        }
    }
}

// ---------------- kernel 1: per-batch exact top-K via radix histogram ----------------
extern "C" __global__ __launch_bounds__(1024)
void topk_kernel(const float* __restrict__ predict, float* __restrict__ out, int write_idx) {
    __shared__ int hist[2048];
    __shared__ int partial[64];
    __shared__ unsigned long long cand[2048];
    __shared__ unsigned char flag[HWSZ];
    __shared__ int scanbuf[1024];
    __shared__ int s_bin, s_before, s_cnt;

    const int b = blockIdx.x;
    const int tid = threadIdx.x;
    const float* sc = predict + (size_t)b * 3 * HWSZ;

    for (int i = tid; i < 2048; i += 1024) hist[i] = 0;
    for (int i = tid; i < HWSZ; i += 1024) { flag[i] = 0; g_pos[b * HWSZ + i] = -1; }
    if (tid == 0) s_cnt = 0;
    __syncthreads();

    for (int i = tid; i < HWSZ; i += 1024)
        atomicAdd(&hist[desckey(sc[i]) >> 21], 1);
    __syncthreads();

    if (tid < 64) {
        int s = 0;
        #pragma unroll
        for (int j = 0; j < 32; j++) s += hist[tid * 32 + j];
        partial[tid] = s;
    }
    __syncthreads();
    if (tid == 0) {
        int run = 0;
        for (int t = 0; t < 64; t++) { int v = partial[t]; partial[t] = run; run += v; }
    }
    __syncthreads();
    if (tid < 64) {
        int run = partial[tid];
        #pragma unroll
        for (int j = 0; j < 32; j++) { run += hist[tid * 32 + j]; hist[tid * 32 + j] = run; }
    }
    __syncthreads();

    for (int bin = tid; bin < 2048; bin += 1024) {
        int c = hist[bin];
        int cb = (bin == 0) ? 0 : hist[bin - 1];
        if (c >= KSEL && cb < KSEL) { s_bin = bin; s_before = cb; }
    }
    __syncthreads();
    const int Bb = s_bin;
    const int r = KSEL - s_before;

    for (int i = tid; i < HWSZ; i += 1024) {
        unsigned k = desckey(sc[i]);
        if ((int)(k >> 21) == Bb) {
            int slot = atomicAdd(&s_cnt, 1);
            if (slot < 2048) cand[slot] = (((unsigned long long)k) << 32) | (unsigned)i;
        }
    }
    __syncthreads();
    int cnt = s_cnt; if (cnt > 2048) cnt = 2048;
    for (int i = tid; i < 2048; i += 1024)
        if (i >= cnt) cand[i] = 0xFFFFFFFFFFFFFFFFULL;
    __syncthreads();

    for (int size = 2; size <= 2048; size <<= 1) {
        for (int stride = size >> 1; stride > 0; stride >>= 1) {
            for (int i = tid; i < 2048; i += 1024) {
                int j = i ^ stride;
                if (j > i) {
                    unsigned long long a = cand[i], c = cand[j];
                    bool up = ((i & size) == 0);
                    if ((a > c) == up) { cand[i] = c; cand[j] = a; }
                }
            }
            __syncthreads();
        }
    }
    for (int j = tid; j < r; j += 1024)
        flag[(int)(cand[j] & 0xFFFFFFFFu)] = 1;
    __syncthreads();

    const int lo = tid * 8;
    int mycnt = 0;
    #pragma unroll
    for (int q = 0; q < 8; q++) {
        int i = lo + q;
        if (i < HWSZ) {
            int bin = desckey(sc[i]) >> 21;
            if (bin < Bb || flag[i]) mycnt++;
        }
    }
    scanbuf[tid] = mycnt;
    __syncthreads();
    for (int off = 1; off < 1024; off <<= 1) {
        int v = (tid >= off) ? scanbuf[tid - off] : 0;
        __syncthreads();
        scanbuf[tid] += v;
        __syncthreads();
    }
    int pos = scanbuf[tid] - mycnt;
    #pragma unroll
    for (int q = 0; q < 8; q++) {
        int i = lo + q;
        if (i < HWSZ) {
            int bin = desckey(sc[i]) >> 21;
            if (bin < Bb || flag[i]) {
                g_sorted_idx[b * KSEL + pos] = i;
                g_pos[b * HWSZ + i] = pos;
                if (write_idx) out[(size_t)NROWS * ND + b * KSEL + pos] = (float)i;
                pos++;
            }
        }
    }
}

// ---------------- 3xFP16-split tensor-core GEMM, fused gather for A ----------------
#define MMA_F16(acc, a0, a1, a2, a3, b0, b1)                                    \
    asm volatile(                                                               \
        "mma.sync.aligned.m16n8k16.row.col.f32.f16.f16.f32 "                    \
        "{%0,%1,%2,%3}, {%4,%5,%6,%7}, {%8,%9}, {%0,%1,%2,%3};"                 \
        : "+f"(acc[0]), "+f"(acc[1]), "+f"(acc[2]), "+f"(acc[3])                \
        : "r"(a0), "r"(a1), "r"(a2), "r"(a3), "r"(b0), "r"(b1))

template <int KD, bool GATHER>
__device__ __forceinline__ void gemm_body(const float* __restrict__ Asrc,
                                          const unsigned* __restrict__ BH,
                                          const unsigned* __restrict__ BL,
                                          float* __restrict__ C,
                                          const float* __restrict__ feat) {
    constexpr int K2 = KD / 2;
    __shared__ unsigned AsH[128 * 20], AsL[128 * 20];   // [m][k2(16)] pad 20
    __shared__ unsigned BsH[128 * 20], BsL[128 * 20];   // [n][k2(16)] pad 20
    __shared__ int s_off[128];

    const int tid  = threadIdx.x;            // 256 = 8 warps
    const int lane = tid & 31;
    const int warp = tid >> 5;
    const int wm = (warp & 3) * 32;
    const int wn = (warp >> 2) * 64;
    const int gm = blockIdx.x * 128;

    const int arow = tid >> 1;
    const int ahalf = tid & 1;               // 16-channel half

    if (GATHER && tid < 128) {
        int i = g_sorted_idx[gm + tid];
        int b = (gm + tid) / KSEL;
        s_off[tid] = b * (CH * HWSZ) + (i % HH) * WW + (i / HH);
    }
    __syncthreads();

    float acc[2][8][4];
    #pragma unroll
    for (int mt = 0; mt < 2; mt++)
        #pragma unroll
        for (int nt = 0; nt < 8; nt++)
            #pragma unroll
            for (int q = 0; q < 4; q++) acc[mt][nt][q] = 0.0f;

    float v[16];
    uint4 bh0, bh1, bl0, bl1;
    const int brow = tid >> 1, bkb = (tid & 1) * 8;

    // preload tile 0
    {
        const int cb = ahalf * 16;
        if (GATHER) {
            #pragma unroll
            for (int j = 0; j < 16; j++) {
                float t = feat[(size_t)s_off[arow] + (size_t)(cb + j) * HWSZ];
                v[j] = fminf(fmaxf(t, 0.0f), 6.0f);
            }
        } else {
            #pragma unroll
            for (int q = 0; q < 4; q++) {
                float4 t = *(const float4*)&Asrc[(size_t)(gm + arow) * KD + cb + q * 4];
                v[q * 4] = t.x; v[q * 4 + 1] = t.y; v[q * 4 + 2] = t.z; v[q * 4 + 3] = t.w;
            }
        }
        const uint4* ph = (const uint4*)&BH[brow * K2 + bkb];
        const uint4* pl = (const uint4*)&BL[brow * K2 + bkb];
        bh0 = ph[0]; bh1 = ph[1]; bl0 = pl[0]; bl1 = pl[1];
    }

    for (int k0 = 0; k0 < KD; k0 += 32) {
        __syncthreads();   // previous tile's smem reads done
        // store A split
        #pragma unroll
        for (int jj = 0; jj < 8; jj++) {
            int kidx = arow * 20 + ahalf * 8 + jj;
            AsH[kidx] = pack_split_hi(v[2 * jj], v[2 * jj + 1]);
            AsL[kidx] = pack_split_lo(v[2 * jj], v[2 * jj + 1]);
        }
        // store B
        {
            int base = brow * 20 + bkb;
            BsH[base + 0] = bh0.x; BsH[base + 1] = bh0.y; BsH[base + 2] = bh0.z; BsH[base + 3] = bh0.w;
            BsH[base + 4] = bh1.x; BsH[base + 5] = bh1.y; BsH[base + 6] = bh1.z; BsH[base + 7] = bh1.w;
            BsL[base + 0] = bl0.x; BsL[base + 1] = bl0.y; BsL[base + 2] = bl0.z; BsL[base + 3] = bl0.w;
            BsL[base + 4] = bl1.x; BsL[base + 5] = bl1.y; BsL[base + 6] = bl1.z; BsL[base + 7] = bl1.w;
        }
        __syncthreads();

        // prefetch next tile (LDGs overlap the MMA block below)
        if (k0 + 32 < KD) {
            const int cb = k0 + 32 + ahalf * 16;
            if (GATHER) {
                #pragma unroll
                for (int j = 0; j < 16; j++) {
                    float t = feat[(size_t)s_off[arow] + (size_t)(cb + j) * HWSZ];
                    v[j] = fminf(fmaxf(t, 0.0f), 6.0f);
                }
            } else {
                #pragma unroll
                for (int q = 0; q < 4; q++) {
                    float4 t = *(const float4*)&Asrc[(size_t)(gm + arow) * KD + cb + q * 4];
                    v[q * 4] = t.x; v[q * 4 + 1] = t.y; v[q * 4 + 2] = t.z; v[q * 4 + 3] = t.w;
                }
            }
            int k2n = (k0 + 32) / 2;
            const uint4* ph = (const uint4*)&BH[brow * K2 + k2n + bkb];
            const uint4* pl = (const uint4*)&BL[brow * K2 + k2n + bkb];
            bh0 = ph[0]; bh1 = ph[1]; bl0 = pl[0]; bl1 = pl[1];
        }

        #pragma unroll
        for (int ks = 0; ks < 2; ks++) {
            const int kf = ks * 8 + (lane & 3);
            unsigned aH[2][4], aL[2][4], bHf[8][2], bLf[8][2];
            #pragma unroll
            for (int mt = 0; mt < 2; mt++) {
                int m0 = wm + mt * 16 + (lane >> 2);
                aH[mt][0] = AsH[m0 * 20 + kf];
                aH[mt][1] = AsH[(m0 + 8) * 20 + kf];
                aH[mt][2] = AsH[m0 * 20 + kf + 4];
                aH[mt][3] = AsH[(m0 + 8) * 20 + kf + 4];
                aL[mt][0] = AsL[m0 * 20 + kf];
                aL[mt][1] = AsL[(m0 + 8) * 20 + kf];
                aL[mt][2] = AsL[m0 * 20 + kf + 4];
                aL[mt][3] = AsL[(m0 + 8) * 20 + kf + 4];
            }
            #pragma unroll
            for (int nt = 0; nt < 8; nt++) {
                int n0 = wn + nt * 8 + (lane >> 2);
                bHf[nt][0] = BsH[n0 * 20 + kf];
                bHf[nt][1] = BsH[n0 * 20 + kf + 4];
                bLf[nt][0] = BsL[n0 * 20 + kf];
                bLf[nt][1] = BsL[n0 * 20 + kf + 4];
            }
            #pragma unroll
            for (int mt = 0; mt < 2; mt++)
                #pragma unroll
                for (int nt = 0; nt < 8; nt++) {
                    MMA_F16(acc[mt][nt], aL[mt][0], aL[mt][1], aL[mt][2], aL[mt][3],
                            bHf[nt][0], bHf[nt][1]);
                    MMA_F16(acc[mt][nt], aH[mt][0], aH[mt][1], aH[mt][2], aH[mt][3],
                            bLf[nt][0], bLf[nt][1]);
                    MMA_F16(acc[mt][nt], aH[mt][0], aH[mt][1], aH[mt][2], aH[mt][3],
                            bHf[nt][0], bHf[nt][1]);
                }
        }
    }

    #pragma unroll
    for (int mt = 0; mt < 2; mt++) {
        int row0 = gm + wm + mt * 16 + (lane >> 2);
        int colb = (lane & 3) * 2;
        #pragma unroll
        for (int nt = 0; nt < 8; nt++) {
            int col = wn + nt * 8 + colb;
            *(float2*)&C[(size_t)row0 * ND + col] =
                make_float2(acc[mt][nt][0], acc[mt][nt][1]);
            *(float2*)&C[(size_t)(row0 + 8) * ND + col] =
                make_float2(acc[mt][nt][2], acc[mt][nt][3]);
        }
    }
}

extern "C" __global__ __launch_bounds__(256)
void gemm1_kernel(const float* __restrict__ feat) {
    gemm_body<CH, true>(nullptr, g_w1h, g_w1l, g_g1, feat);
}

extern "C" __global__ __launch_bounds__(256)
void gemm2_kernel() {
    gemm_body<ND, false>(g_x1, g_w2h, g_w2l, g_g2, nullptr);
}

// ---------------- sparse 3x3 neighbor sums (warp per row, float4 lanes) ----------------
extern "C" __global__ __launch_bounds__(256)
void nsum1_kernel(const float* __restrict__ b1) {
    const int row = blockIdx.x * 8 + (threadIdx.x >> 5);
    const int lane = threadIdx.x & 31;
    const int b = row / KSEL, k = row - b * KSEL;
    const int i = g_sorted_idx[row];
    const int py = i / WW, px = i % WW;
    int nb = -1;
    if (lane < 9) {
        int ny = py + lane / 3 - 1, nx = px + lane % 3 - 1;
        if ((unsigned)ny < HH && (unsigned)nx < WW)
            nb = g_pos[b * HWSZ + ny * WW + nx];
    }
    float4 acc = *(const float4*)&b1[(size_t)k * ND + lane * 4];
    #pragma unroll
    for (int j = 0; j < 9; j++) {
        int n = __shfl_sync(0xFFFFFFFFu, nb, j);
        if (n >= 0) {
            float4 v = *(const float4*)&g_g1[(size_t)(b * KSEL + n) * ND + lane * 4];
            acc.x += v.x; acc.y += v.y; acc.z += v.z; acc.w += v.w;
        }
    }
    *(float4*)&g_x1[(size_t)row * ND + lane * 4] = acc;
}

extern "C" __global__ __launch_bounds__(256)
void final_kernel(const float* __restrict__ b2, float* __restrict__ out) {
    const int row = blockIdx.x * 8 + (threadIdx.x >> 5);
    const int lane = threadIdx.x & 31;
    const int b = row / KSEL, k = row - b * KSEL;
    const int i = g_sorted_idx[row];
    const int py = i / WW, px = i % WW;
    int nb = -1;
    if (lane < 9) {
        int ny = py + lane / 3 - 1, nx = px + lane % 3 - 1;
        if ((unsigned)ny < HH && (unsigned)nx < WW)
            nb = g_pos[b * HWSZ + ny * WW + nx];
    }
    float4 acc = *(const float4*)&b2[(size_t)k * ND + lane * 4];
    float4 x1v = *(const float4*)&g_x1[(size_t)row * ND + lane * 4];
    acc.x += x1v.x; acc.y += x1v.y; acc.z += x1v.z; acc.w += x1v.w;
    #pragma unroll
    for (int j = 0; j < 9; j++) {
        int n = __shfl_sync(0xFFFFFFFFu, nb, j);
        if (n >= 0) {
            float4 v = *(const float4*)&g_g2[(size_t)(b * KSEL + n) * ND + lane * 4];
            acc.x += v.x; acc.y += v.y; acc.z += v.z; acc.w += v.w;
        }
    }
    float4 o = make_float4(tanhf(acc.x), tanhf(acc.y), tanhf(acc.z), tanhf(acc.w));
    *(float4*)&out[(size_t)row * ND + lane * 4] = o;
}

// ---------------- launch ----------------
extern "C" void kernel_launch(void* const* d_in, const int* in_sizes, int n_in,
                              void* d_out, int out_size) {
    const float* feat = (const float*)d_in[0];   // (8,512,75,100)
    const float* pred = (const float*)d_in[1];   // (8,3,75,100)
    const float* w1   = (const float*)d_in[2];   // (512,128)
    const float* b1   = (const float*)d_in[3];   // (2000,128)
    const float* w2   = (const float*)d_in[4];   // (128,128)
    const float* b2   = (const float*)d_in[5];   // (2000,128)
    float* out = (float*)d_out;

    const int feat_elems = NROWS * ND;
    const int write_idx = (out_size >= feat_elems + NROWS) ? 1 : 0;

    prep_kernel<<<(ND * (CH / 2) + ND * (ND / 2) + 255) / 256, 256>>>(w1, w2);
    topk_kernel<<<NB, 1024>>>(pred, out, write_idx);
    gemm1_kernel<<<NROWS / 128, 256>>>(feat);
    nsum1_kernel<<<NROWS / 8, 256>>>(b1);
    gemm2_kernel<<<NROWS / 128, 256>>>();
    final_kernel<<<NROWS / 8, 256>>>(b2, out);
}

// round 6
// speedup vs baseline: 2.0686x; 1.0361x over previous
#include <cuda_runtime.h>
#include <cuda_fp16.h>
#include <stdint.h>
#include <math.h>

#define KSEL 2000
#define HH 75
#define WW 100
#define HWSZ 7500
#define NB 8
#define CH 512
#define ND 128
#define NROWS (NB * KSEL)
#define CPAIRS (CH / 2)     // 256
#define KPAD 2048           // per-batch padded row count

// ---------------- scratch (static device allocations) ----------------
__device__ int      g_sorted_idx[NROWS];
__device__ int      g_pos[NB * HWSZ];
__device__ int      g_addr[NB * KPAD];              // plane address per row (-1 = pad)
__device__ unsigned g_nfh[(size_t)NB * CPAIRS * KPAD];  // A hi half2 [b][c2][k]
__device__ unsigned g_nfl[(size_t)NB * CPAIRS * KPAD];  // A lo half2
__device__ float    g_g1[NROWS * ND];
__device__ float    g_x1[NROWS * ND];
__device__ float    g_g2[NROWS * ND];
__device__ unsigned g_w1h[ND * (CH / 2)];           // [n][k2]
__device__ unsigned g_w1l[ND * (CH / 2)];
__device__ unsigned g_w2h[ND * (ND / 2)];
__device__ unsigned g_w2l[ND * (ND / 2)];

__device__ __forceinline__ unsigned desckey(float f) {
    unsigned u = __float_as_uint(f);
    unsigned ord = (u & 0x80000000u) ? ~u : (u ^ 0x80000000u);
    return ~ord;
}
__device__ __forceinline__ unsigned pack_split_hi(float v0, float v1) {
    __half h0 = __float2half_rn(v0), h1 = __float2half_rn(v1);
    return (unsigned)__half_as_ushort(h0) | ((unsigned)__half_as_ushort(h1) << 16);
}
__device__ __forceinline__ unsigned pack_split_lo(float v0, float v1) {
    __half h0 = __float2half_rn(v0), h1 = __float2half_rn(v1);
    __half l0 = __float2half_rn(v0 - __half2float(h0));
    __half l1 = __float2half_rn(v1 - __half2float(h1));
    return (unsigned)__half_as_ushort(l0) | ((unsigned)__half_as_ushort(l1) << 16);
}
__device__ __forceinline__ uint32_t s2u(const void* p) {
    return (uint32_t)__cvta_generic_to_shared(p);
}

// ---------------- weight split prep ----------------
extern "C" __global__ __launch_bounds__(256)
void prep_kernel(const float* __restrict__ w1, const float* __restrict__ w2) {
    int idx = blockIdx.x * 256 + threadIdx.x;
    const int N1 = ND * (CH / 2);
    if (idx < N1) {
        int f = idx % ND, c2 = idx / ND;
        float v0 = w1[(2 * c2) * ND + f], v1 = w1[(2 * c2 + 1) * ND + f];
        g_w1h[f * (CH / 2) + c2] = pack_split_hi(v0, v1);
        g_w1l[f * (CH / 2) + c2] = pack_split_lo(v0, v1);
    } else {
        int j = idx - N1;
        if (j < ND * (ND / 2)) {
            int f = j % ND, c2 = j / ND;
            float v0 = w2[(2 * c2) * ND + f], v1 = w2[(2 * c2 + 1) * ND + f];
            g_w2h[f * (ND / 2) + c2] = pack_split_hi(v0, v1);
            g_w2l[f * (ND / 2) + c2] = pack_split_lo(v0, v1);
        }
    }
}

// ---------------- kernel 1: per-batch exact top-K via radix histogram ----------------
extern "C" __global__ __launch_bounds__(1024)
void topk_kernel(const float* __restrict__ predict, float* __restrict__ out, int write_idx) {
    __shared__ int hist[2048];
    __shared__ int partial[64];
    __shared__ unsigned long long cand[2048];
    __shared__ unsigned char flag[HWSZ];
    __shared__ int scanbuf[1024];
    __shared__ int s_bin, s_before, s_cnt;

    const int b = blockIdx.x;
    const int tid = threadIdx.x;
    const float* sc = predict + (size_t)b * 3 * HWSZ;

    for (int i = tid; i < 2048; i += 1024) hist[i] = 0;
    for (int i = tid; i < HWSZ; i += 1024) { flag[i] = 0; g_pos[b * HWSZ + i] = -1; }
    if (tid < KPAD - KSEL) g_addr[b * KPAD + KSEL + tid] = -1;   // pad rows
    if (tid == 0) s_cnt = 0;
    __syncthreads();

    for (int i = tid; i < HWSZ; i += 1024)
        atomicAdd(&hist[desckey(sc[i]) >> 21], 1);
    __syncthreads();

    if (tid < 64) {
        int s = 0;
        #pragma unroll
        for (int j = 0; j < 32; j++) s += hist[tid * 32 + j];
        partial[tid] = s;
    }
    __syncthreads();
    if (tid == 0) {
        int run = 0;
        for (int t = 0; t < 64; t++) { int v = partial[t]; partial[t] = run; run += v; }
    }
    __syncthreads();
    if (tid < 64) {
        int run = partial[tid];
        #pragma unroll
        for (int j = 0; j < 32; j++) { run += hist[tid * 32 + j]; hist[tid * 32 + j] = run; }
    }
    __syncthreads();

    for (int bin = tid; bin < 2048; bin += 1024) {
        int c = hist[bin];
        int cb = (bin == 0) ? 0 : hist[bin - 1];
        if (c >= KSEL && cb < KSEL) { s_bin = bin; s_before = cb; }
    }
    __syncthreads();
    const int Bb = s_bin;
    const int r = KSEL - s_before;

    for (int i = tid; i < HWSZ; i += 1024) {
        unsigned k = desckey(sc[i]);
        if ((int)(k >> 21) == Bb) {
            int slot = atomicAdd(&s_cnt, 1);
            if (slot < 2048) cand[slot] = (((unsigned long long)k) << 32) | (unsigned)i;
        }
    }
    __syncthreads();
    int cnt = s_cnt; if (cnt > 2048) cnt = 2048;
    for (int i = tid; i < 2048; i += 1024)
        if (i >= cnt) cand[i] = 0xFFFFFFFFFFFFFFFFULL;
    __syncthreads();

    for (int size = 2; size <= 2048; size <<= 1) {
        for (int stride = size >> 1; stride > 0; stride >>= 1) {
            for (int i = tid; i < 2048; i += 1024) {
                int j = i ^ stride;
                if (j > i) {
                    unsigned long long a = cand[i], c = cand[j];
                    bool up = ((i & size) == 0);
                    if ((a > c) == up) { cand[i] = c; cand[j] = a; }
                }
            }
            __syncthreads();
        }
    }
    for (int j = tid; j < r; j += 1024)
        flag[(int)(cand[j] & 0xFFFFFFFFu)] = 1;
    __syncthreads();

    const int lo = tid * 8;
    int mycnt = 0;
    #pragma unroll
    for (int q = 0; q < 8; q++) {
        int i = lo + q;
        if (i < HWSZ) {
            int bin = desckey(sc[i]) >> 21;
            if (bin < Bb || flag[i]) mycnt++;
        }
    }
    scanbuf[tid] = mycnt;
    __syncthreads();
    for (int off = 1; off < 1024; off <<= 1) {
        int v = (tid >= off) ? scanbuf[tid - off] : 0;
        __syncthreads();
        scanbuf[tid] += v;
        __syncthreads();
    }
    int pos = scanbuf[tid] - mycnt;
    #pragma unroll
    for (int q = 0; q < 8; q++) {
        int i = lo + q;
        if (i < HWSZ) {
            int bin = desckey(sc[i]) >> 21;
            if (bin < Bb || flag[i]) {
                g_sorted_idx[b * KSEL + pos] = i;
                g_pos[b * HWSZ + i] = pos;
                g_addr[b * KPAD + pos] = (i % HH) * WW + i / HH;
                if (write_idx) out[(size_t)NROWS * ND + b * KSEL + pos] = (float)i;
                pos++;
            }
        }
    }
}

// ---------------- kernel 2: bulk-copy gather + clip + fp16 split ----------------
// CTA per (b, channel-pair). Two cp.async.bulk 30KB plane loads -> smem,
// then scatter-read selected positions, write split half2 k-major.
extern "C" __global__ __launch_bounds__(256)
void gather_kernel(const float* __restrict__ feat) {
    extern __shared__ float sp[];                  // 15000 floats (2 planes)
    __shared__ __align__(8) unsigned long long mbar;
    const int blk = blockIdx.x;
    const int b = blk >> 8, c2 = blk & 255;
    const int tid = threadIdx.x;
    const uint32_t mb = s2u(&mbar);

    if (tid == 0)
        asm volatile("mbarrier.init.shared.b64 [%0], %1;" :: "r"(mb), "r"(1) : "memory");
    __syncthreads();
    if (tid == 0) {
        asm volatile("mbarrier.arrive.expect_tx.shared.b64 _, [%0], %1;"
                     :: "r"(mb), "r"(60000) : "memory");
        const float* src = feat + ((size_t)b * CH + 2 * c2) * HWSZ;
        uint32_t d0 = s2u(sp);
        asm volatile("cp.async.bulk.shared::cluster.global.mbarrier::complete_tx::bytes "
                     "[%0], [%1], %2, [%3];"
                     :: "r"(d0), "l"(src), "r"(30000), "r"(mb) : "memory");
        asm volatile("cp.async.bulk.shared::cluster.global.mbarrier::complete_tx::bytes "
                     "[%0], [%1], %2, [%3];"
                     :: "r"(d0 + 30000), "l"(src + HWSZ), "r"(30000), "r"(mb) : "memory");
    }
    asm volatile(
        "{\n\t.reg .pred P;\n"
        "LW%=:\n\t mbarrier.try_wait.parity.acquire.cta.shared::cta.b64 P, [%0], %1;\n"
        "\t@P bra LD%=;\n\t bra LW%=;\n"
        "LD%=:\n\t}" :: "r"(mb), "r"(0) : "memory");

    const int kb = b * KPAD;
    const size_t oh = ((size_t)b * CPAIRS + c2) * KPAD;
    #pragma unroll
    for (int q = 0; q < 2; q++) {
        int k0 = tid * 8 + q * 4;
        unsigned h[4], l[4];
        #pragma unroll
        for (int j = 0; j < 4; j++) {
            int a = g_addr[kb + k0 + j];
            float v0 = 0.0f, v1 = 0.0f;
            if (a >= 0) {
                v0 = fminf(fmaxf(sp[a], 0.0f), 6.0f);
                v1 = fminf(fmaxf(sp[HWSZ + a], 0.0f), 6.0f);
            }
            h[j] = pack_split_hi(v0, v1);
            l[j] = pack_split_lo(v0, v1);
        }
        *(uint4*)&g_nfh[oh + k0] = make_uint4(h[0], h[1], h[2], h[3]);
        *(uint4*)&g_nfl[oh + k0] = make_uint4(l[0], l[1], l[2], l[3]);
    }
}

// ---------------- 3xFP16-split MMA helpers ----------------
#define MMA_F16(acc, a0, a1, a2, a3, b0, b1)                                    \
    asm volatile(                                                               \
        "mma.sync.aligned.m16n8k16.row.col.f32.f16.f16.f32 "                    \
        "{%0,%1,%2,%3}, {%4,%5,%6,%7}, {%8,%9}, {%0,%1,%2,%3};"                 \
        : "+f"(acc[0]), "+f"(acc[1]), "+f"(acc[2]), "+f"(acc[3])                \
        : "r"(a0), "r"(a1), "r"(a2), "r"(a3), "r"(b0), "r"(b1))

// ---------------- gemm1: g1 = nf @ w1  (A from split k-major arrays) ----------------
extern "C" __global__ __launch_bounds__(256)
void gemm1_kernel() {
    __shared__ unsigned AsH[128 * 20], AsL[128 * 20];
    __shared__ unsigned BsH[128 * 20], BsL[128 * 20];
    const int tid  = threadIdx.x;
    const int lane = tid & 31;
    const int warp = tid >> 5;
    const int wm = (warp & 3) * 32;
    const int wn = (warp >> 2) * 64;
    const int b = blockIdx.x >> 4;            // batch
    const int t = blockIdx.x & 15;            // m-tile within batch

    const int c2i = tid & 15;                 // A: channel-pair within k-tile
    const int m0l = (tid >> 4) * 4;           // A: m base (q adds +64)
    const int brow = tid >> 1, bkb = (tid & 1) * 8;

    float acc[2][8][4];
    #pragma unroll
    for (int mt = 0; mt < 2; mt++)
        #pragma unroll
        for (int nt = 0; nt < 8; nt++)
            #pragma unroll
            for (int q = 0; q < 4; q++) acc[mt][nt][q] = 0.0f;

    uint4 ah[2], al[2], bh[2], bl[2];
    const size_t abase = ((size_t)b * CPAIRS) * KPAD + t * 128;

    // preload k-tile 0 (each thread: 2 uint4 of A(hi,lo), 2 uint4 of B(hi,lo))
    #pragma unroll
    for (int q = 0; q < 2; q++) {
        size_t ai = abase + (size_t)c2i * KPAD + m0l + q * 64;
        ah[q] = *(const uint4*)&g_nfh[ai];
        al[q] = *(const uint4*)&g_nfl[ai];
    }
    bh[0] = *(const uint4*)&g_w1h[brow * (CH / 2) + bkb];
    bh[1] = *(const uint4*)&g_w1h[brow * (CH / 2) + bkb + 4];
    bl[0] = *(const uint4*)&g_w1l[brow * (CH / 2) + bkb];
    bl[1] = *(const uint4*)&g_w1l[brow * (CH / 2) + bkb + 4];

    for (int kt = 0; kt < 16; kt++) {
        __syncthreads();
        #pragma unroll
        for (int q = 0; q < 2; q++) {
            int m = m0l + q * 64;
            AsH[(m + 0) * 20 + c2i] = ah[q].x;
            AsH[(m + 1) * 20 + c2i] = ah[q].y;
            AsH[(m + 2) * 20 + c2i] = ah[q].z;
            AsH[(m + 3) * 20 + c2i] = ah[q].w;
            AsL[(m + 0) * 20 + c2i] = al[q].x;
            AsL[(m + 1) * 20 + c2i] = al[q].y;
            AsL[(m + 2) * 20 + c2i] = al[q].z;
            AsL[(m + 3) * 20 + c2i] = al[q].w;
        }
        {
            int base = brow * 20 + bkb;
            BsH[base + 0] = bh[0].x; BsH[base + 1] = bh[0].y;
            BsH[base + 2] = bh[0].z; BsH[base + 3] = bh[0].w;
            BsH[base + 4] = bh[1].x; BsH[base + 5] = bh[1].y;
            BsH[base + 6] = bh[1].z; BsH[base + 7] = bh[1].w;
            BsL[base + 0] = bl[0].x; BsL[base + 1] = bl[0].y;
            BsL[base + 2] = bl[0].z; BsL[base + 3] = bl[0].w;
            BsL[base + 4] = bl[1].x; BsL[base + 5] = bl[1].y;
            BsL[base + 6] = bl[1].z; BsL[base + 7] = bl[1].w;
        }
        __syncthreads();

        if (kt + 1 < 16) {
            const size_t an = abase + (size_t)((kt + 1) * 16 + c2i) * KPAD + m0l;
            #pragma unroll
            for (int q = 0; q < 2; q++) {
                ah[q] = *(const uint4*)&g_nfh[an + q * 64];
                al[q] = *(const uint4*)&g_nfl[an + q * 64];
            }
            int k2n = (kt + 1) * 16;
            bh[0] = *(const uint4*)&g_w1h[brow * (CH / 2) + k2n + bkb];
            bh[1] = *(const uint4*)&g_w1h[brow * (CH / 2) + k2n + bkb + 4];
            bl[0] = *(const uint4*)&g_w1l[brow * (CH / 2) + k2n + bkb];
            bl[1] = *(const uint4*)&g_w1l[brow * (CH / 2) + k2n + bkb + 4];
        }

        #pragma unroll
        for (int ks = 0; ks < 2; ks++) {
            const int kf = ks * 8 + (lane & 3);
            unsigned aH[2][4], aL[2][4], bHf[8][2], bLf[8][2];
            #pragma unroll
            for (int mt = 0; mt < 2; mt++) {
                int m0 = wm + mt * 16 + (lane >> 2);
                aH[mt][0] = AsH[m0 * 20 + kf];
                aH[mt][1] = AsH[(m0 + 8) * 20 + kf];
                aH[mt][2] = AsH[m0 * 20 + kf + 4];
                aH[mt][3] = AsH[(m0 + 8) * 20 + kf + 4];
                aL[mt][0] = AsL[m0 * 20 + kf];
                aL[mt][1] = AsL[(m0 + 8) * 20 + kf];
                aL[mt][2] = AsL[m0 * 20 + kf + 4];
                aL[mt][3] = AsL[(m0 + 8) * 20 + kf + 4];
            }
            #pragma unroll
            for (int nt = 0; nt < 8; nt++) {
                int n0 = wn + nt * 8 + (lane >> 2);
                bHf[nt][0] = BsH[n0 * 20 + kf];
                bHf[nt][1] = BsH[n0 * 20 + kf + 4];
                bLf[nt][0] = BsL[n0 * 20 + kf];
                bLf[nt][1] = BsL[n0 * 20 + kf + 4];
            }
            #pragma unroll
            for (int mt = 0; mt < 2; mt++)
                #pragma unroll
                for (int nt = 0; nt < 8; nt++) {
                    MMA_F16(acc[mt][nt], aL[mt][0], aL[mt][1], aL[mt][2], aL[mt][3],
                            bHf[nt][0], bHf[nt][1]);
                    MMA_F16(acc[mt][nt], aH[mt][0], aH[mt][1], aH[mt][2], aH[mt][3],
                            bLf[nt][0], bLf[nt][1]);
                    MMA_F16(acc[mt][nt], aH[mt][0], aH[mt][1], aH[mt][2], aH[mt][3],
                            bHf[nt][0], bHf[nt][1]);
                }
        }
    }

    #pragma unroll
    for (int mt = 0; mt < 2; mt++) {
        int rk = t * 128 + wm + mt * 16 + (lane >> 2);
        int colb = (lane & 3) * 2;
        #pragma unroll
        for (int nt = 0; nt < 8; nt++) {
            int col = wn + nt * 8 + colb;
            if (rk < KSEL)
                *(float2*)&g_g1[(size_t)(b * KSEL + rk) * ND + col] =
                    make_float2(acc[mt][nt][0], acc[mt][nt][1]);
            if (rk + 8 < KSEL)
                *(float2*)&g_g1[(size_t)(b * KSEL + rk + 8) * ND + col] =
                    make_float2(acc[mt][nt][2], acc[mt][nt][3]);
        }
    }
}

// ---------------- gemm2: g2 = x1 @ w2 (A fp32 rows, split on the fly) ----------------
extern "C" __global__ __launch_bounds__(256)
void gemm2_kernel() {
    __shared__ unsigned AsH[128 * 20], AsL[128 * 20];
    __shared__ unsigned BsH[128 * 20], BsL[128 * 20];
    const int tid  = threadIdx.x;
    const int lane = tid & 31;
    const int warp = tid >> 5;
    const int wm = (warp & 3) * 32;
    const int wn = (warp >> 2) * 64;
    const int gm = blockIdx.x * 128;
    const int K2 = ND / 2;

    const int arow = tid >> 1, ahalf = tid & 1;
    const int brow = tid >> 1, bkb = (tid & 1) * 8;

    float acc[2][8][4];
    #pragma unroll
    for (int mt = 0; mt < 2; mt++)
        #pragma unroll
        for (int nt = 0; nt < 8; nt++)
            #pragma unroll
            for (int q = 0; q < 4; q++) acc[mt][nt][q] = 0.0f;

    float v[16];
    uint4 bh[2], bl[2];
    {
        const int cb = ahalf * 16;
        #pragma unroll
        for (int q = 0; q < 4; q++) {
            float4 tv = *(const float4*)&g_x1[(size_t)(gm + arow) * ND + cb + q * 4];
            v[q * 4] = tv.x; v[q * 4 + 1] = tv.y; v[q * 4 + 2] = tv.z; v[q * 4 + 3] = tv.w;
        }
        bh[0] = *(const uint4*)&g_w2h[brow * K2 + bkb];
        bh[1] = *(const uint4*)&g_w2h[brow * K2 + bkb + 4];
        bl[0] = *(const uint4*)&g_w2l[brow * K2 + bkb];
        bl[1] = *(const uint4*)&g_w2l[brow * K2 + bkb + 4];
    }

    for (int k0 = 0; k0 < ND; k0 += 32) {
        __syncthreads();
        #pragma unroll
        for (int jj = 0; jj < 8; jj++) {
            int kidx = arow * 20 + ahalf * 8 + jj;
            AsH[kidx] = pack_split_hi(v[2 * jj], v[2 * jj + 1]);
            AsL[kidx] = pack_split_lo(v[2 * jj], v[2 * jj + 1]);
        }
        {
            int base = brow * 20 + bkb;
            BsH[base + 0] = bh[0].x; BsH[base + 1] = bh[0].y;
            BsH[base + 2] = bh[0].z; BsH[base + 3] = bh[0].w;
            BsH[base + 4] = bh[1].x; BsH[base + 5] = bh[1].y;
            BsH[base + 6] = bh[1].z; BsH[base + 7] = bh[1].w;
            BsL[base + 0] = bl[0].x; BsL[base + 1] = bl[0].y;
            BsL[base + 2] = bl[0].z; BsL[base + 3] = bl[0].w;
            BsL[base + 4] = bl[1].x; BsL[base + 5] = bl[1].y;
            BsL[base + 6] = bl[1].z; BsL[base + 7] = bl[1].w;
        }
        __syncthreads();

        if (k0 + 32 < ND) {
            const int cb = k0 + 32 + ahalf * 16;
            #pragma unroll
            for (int q = 0; q < 4; q++) {
                float4 tv = *(const float4*)&g_x1[(size_t)(gm + arow) * ND + cb + q * 4];
                v[q * 4] = tv.x; v[q * 4 + 1] = tv.y; v[q * 4 + 2] = tv.z; v[q * 4 + 3] = tv.w;
            }
            int k2n = (k0 + 32) / 2;
            bh[0] = *(const uint4*)&g_w2h[brow * K2 + k2n + bkb];
            bh[1] = *(const uint4*)&g_w2h[brow * K2 + k2n + bkb + 4];
            bl[0] = *(const uint4*)&g_w2l[brow * K2 + k2n + bkb];
            bl[1] = *(const uint4*)&g_w2l[brow * K2 + k2n + bkb + 4];
        }

        #pragma unroll
        for (int ks = 0; ks < 2; ks++) {
            const int kf = ks * 8 + (lane & 3);
            unsigned aH[2][4], aL[2][4], bHf[8][2], bLf[8][2];
            #pragma unroll
            for (int mt = 0; mt < 2; mt++) {
                int m0 = wm + mt * 16 + (lane >> 2);
                aH[mt][0] = AsH[m0 * 20 + kf];
                aH[mt][1] = AsH[(m0 + 8) * 20 + kf];
                aH[mt][2] = AsH[m0 * 20 + kf + 4];
                aH[mt][3] = AsH[(m0 + 8) * 20 + kf + 4];
                aL[mt][0] = AsL[m0 * 20 + kf];
                aL[mt][1] = AsL[(m0 + 8) * 20 + kf];
                aL[mt][2] = AsL[m0 * 20 + kf + 4];
                aL[mt][3] = AsL[(m0 + 8) * 20 + kf + 4];
            }
            #pragma unroll
            for (int nt = 0; nt < 8; nt++) {
                int n0 = wn + nt * 8 + (lane >> 2);
                bHf[nt][0] = BsH[n0 * 20 + kf];
                bHf[nt][1] = BsH[n0 * 20 + kf + 4];
                bLf[nt][0] = BsL[n0 * 20 + kf];
                bLf[nt][1] = BsL[n0 * 20 + kf + 4];
            }
            #pragma unroll
            for (int mt = 0; mt < 2; mt++)
                #pragma unroll
                for (int nt = 0; nt < 8; nt++) {
                    MMA_F16(acc[mt][nt], aL[mt][0], aL[mt][1], aL[mt][2], aL[mt][3],
                            bHf[nt][0], bHf[nt][1]);
                    MMA_F16(acc[mt][nt], aH[mt][0], aH[mt][1], aH[mt][2], aH[mt][3],
                            bLf[nt][0], bLf[nt][1]);
                    MMA_F16(acc[mt][nt], aH[mt][0], aH[mt][1], aH[mt][2], aH[mt][3],
                            bHf[nt][0], bHf[nt][1]);
                }
        }
    }

    #pragma unroll
    for (int mt = 0; mt < 2; mt++) {
        int row0 = gm + wm + mt * 16 + (lane >> 2);
        int colb = (lane & 3) * 2;
        #pragma unroll
        for (int nt = 0; nt < 8; nt++) {
            int col = wn + nt * 8 + colb;
            *(float2*)&g_g2[(size_t)row0 * ND + col] =
                make_float2(acc[mt][nt][0], acc[mt][nt][1]);
            *(float2*)&g_g2[(size_t)(row0 + 8) * ND + col] =
                make_float2(acc[mt][nt][2], acc[mt][nt][3]);
        }
    }
}

// ---------------- sparse 3x3 neighbor sums ----------------
extern "C" __global__ __launch_bounds__(256)
void nsum1_kernel(const float* __restrict__ b1) {
    const int row = blockIdx.x * 8 + (threadIdx.x >> 5);
    const int lane = threadIdx.x & 31;
    const int b = row / KSEL, k = row - b * KSEL;
    const int i = g_sorted_idx[row];
    const int py = i / WW, px = i % WW;
    int nb = -1;
    if (lane < 9) {
        int ny = py + lane / 3 - 1, nx = px + lane % 3 - 1;
        if ((unsigned)ny < HH && (unsigned)nx < WW)
            nb = g_pos[b * HWSZ + ny * WW + nx];
    }
    float4 acc = *(const float4*)&b1[(size_t)k * ND + lane * 4];
    #pragma unroll
    for (int j = 0; j < 9; j++) {
        int n = __shfl_sync(0xFFFFFFFFu, nb, j);
        if (n >= 0) {
            float4 v = *(const float4*)&g_g1[(size_t)(b * KSEL + n) * ND + lane * 4];
            acc.x += v.x; acc.y += v.y; acc.z += v.z; acc.w += v.w;
        }
    }
    *(float4*)&g_x1[(size_t)row * ND + lane * 4] = acc;
}

extern "C" __global__ __launch_bounds__(256)
void final_kernel(const float* __restrict__ b2, float* __restrict__ out) {
    const int row = blockIdx.x * 8 + (threadIdx.x >> 5);
    const int lane = threadIdx.x & 31;
    const int b = row / KSEL, k = row - b * KSEL;
    const int i = g_sorted_idx[row];
    const int py = i / WW, px = i % WW;
    int nb = -1;
    if (lane < 9) {
        int ny = py + lane / 3 - 1, nx = px + lane % 3 - 1;
        if ((unsigned)ny < HH && (unsigned)nx < WW)
            nb = g_pos[b * HWSZ + ny * WW + nx];
    }
    float4 acc = *(const float4*)&b2[(size_t)k * ND + lane * 4];
    float4 x1v = *(const float4*)&g_x1[(size_t)row * ND + lane * 4];
    acc.x += x1v.x; acc.y += x1v.y; acc.z += x1v.z; acc.w += x1v.w;
    #pragma unroll
    for (int j = 0; j < 9; j++) {
        int n = __shfl_sync(0xFFFFFFFFu, nb, j);
        if (n >= 0) {
            float4 v = *(const float4*)&g_g2[(size_t)(b * KSEL + n) * ND + lane * 4];
            acc.x += v.x; acc.y += v.y; acc.z += v.z; acc.w += v.w;
        }
    }
    float4 o = make_float4(tanhf(acc.x), tanhf(acc.y), tanhf(acc.z), tanhf(acc.w));
    *(float4*)&out[(size_t)row * ND + lane * 4] = o;
}

// ---------------- launch ----------------
extern "C" void kernel_launch(void* const* d_in, const int* in_sizes, int n_in,
                              void* d_out, int out_size) {
    const float* feat = (const float*)d_in[0];
    const float* pred = (const float*)d_in[1];
    const float* w1   = (const float*)d_in[2];
    const float* b1   = (const float*)d_in[3];
    const float* w2   = (const float*)d_in[4];
    const float* b2   = (const float*)d_in[5];
    float* out = (float*)d_out;

    const int feat_elems = NROWS * ND;
    const int write_idx = (out_size >= feat_elems + NROWS) ? 1 : 0;

    cudaFuncSetAttribute((const void*)gather_kernel,
                         cudaFuncAttributeMaxDynamicSharedMemorySize, 60000);

    prep_kernel<<<(ND * (CH / 2) + ND * (ND / 2) + 255) / 256, 256>>>(w1, w2);
    topk_kernel<<<NB, 1024>>>(pred, out, write_idx);
    gather_kernel<<<NB * CPAIRS, 256, 60000>>>(feat);
    gemm1_kernel<<<NB * 16, 256>>>();
    nsum1_kernel<<<NROWS / 8, 256>>>(b1);
    gemm2_kernel<<<NROWS / 8 / 16, 256>>>();   // 125 CTAs
    final_kernel<<<NROWS / 8, 256>>>(b2, out);
}

// round 7
// speedup vs baseline: 2.1627x; 1.0455x over previous
#include <cuda_runtime.h>
#include <cuda_fp16.h>
#include <stdint.h>
#include <math.h>

#define KSEL 2000
#define HH 75
#define WW 100
#define HWSZ 7500
#define NB 8
#define CH 512
#define ND 128
#define NROWS (NB * KSEL)
#define CPAIRS (CH / 2)     // 256
#define KPAD 2048           // per-batch padded row count

// ---------------- scratch (static device allocations) ----------------
__device__ int      g_sorted_idx[NROWS];
__device__ int      g_pos[NB * HWSZ];
__device__ int      g_addr[NB * KPAD];
__device__ unsigned g_nfh[(size_t)NB * CPAIRS * KPAD];  // A hi half2 [b][c2][k]
__device__ unsigned g_nfl[(size_t)NB * CPAIRS * KPAD];  // A lo half2
__device__ float    g_g1[NROWS * ND];
__device__ float    g_x1[NROWS * ND];
__device__ float    g_g2[NROWS * ND];
__device__ unsigned g_w1h[ND * (CH / 2)];               // [n][k2]
__device__ unsigned g_w1l[ND * (CH / 2)];
__device__ unsigned g_w2h[ND * (ND / 2)];
__device__ unsigned g_w2l[ND * (ND / 2)];

__device__ __forceinline__ unsigned desckey(float f) {
    unsigned u = __float_as_uint(f);
    unsigned ord = (u & 0x80000000u) ? ~u : (u ^ 0x80000000u);
    return ~ord;
}
__device__ __forceinline__ unsigned pack_split_hi(float v0, float v1) {
    __half h0 = __float2half_rn(v0), h1 = __float2half_rn(v1);
    return (unsigned)__half_as_ushort(h0) | ((unsigned)__half_as_ushort(h1) << 16);
}
__device__ __forceinline__ unsigned pack_split_lo(float v0, float v1) {
    __half h0 = __float2half_rn(v0), h1 = __float2half_rn(v1);
    __half l0 = __float2half_rn(v0 - __half2float(h0));
    __half l1 = __float2half_rn(v1 - __half2float(h1));
    return (unsigned)__half_as_ushort(l0) | ((unsigned)__half_as_ushort(l1) << 16);
}
__device__ __forceinline__ uint32_t s2u(const void* p) {
    return (uint32_t)__cvta_generic_to_shared(p);
}

// ---------------- weight split prep ----------------
extern "C" __global__ __launch_bounds__(256)
void prep_kernel(const float* __restrict__ w1, const float* __restrict__ w2) {
    int idx = blockIdx.x * 256 + threadIdx.x;
    const int N1 = ND * (CH / 2);
    if (idx < N1) {
        int f = idx % ND, c2 = idx / ND;
        float v0 = w1[(2 * c2) * ND + f], v1 = w1[(2 * c2 + 1) * ND + f];
        g_w1h[f * (CH / 2) + c2] = pack_split_hi(v0, v1);
        g_w1l[f * (CH / 2) + c2] = pack_split_lo(v0, v1);
    } else {
        int j = idx - N1;
        if (j < ND * (ND / 2)) {
            int f = j % ND, c2 = j / ND;
            float v0 = w2[(2 * c2) * ND + f], v1 = w2[(2 * c2 + 1) * ND + f];
            g_w2h[f * (ND / 2) + c2] = pack_split_hi(v0, v1);
            g_w2l[f * (ND / 2) + c2] = pack_split_lo(v0, v1);
        }
    }
}

// ---------------- kernel 1: per-batch exact top-K via radix histogram ----------------
extern "C" __global__ __launch_bounds__(1024)
void topk_kernel(const float* __restrict__ predict, float* __restrict__ out, int write_idx) {
    __shared__ int hist[2048];
    __shared__ int partial[64];
    __shared__ unsigned long long cand[2048];
    __shared__ unsigned char flag[HWSZ];
    __shared__ int scanbuf[1024];
    __shared__ int s_bin, s_before, s_cnt;

    const int b = blockIdx.x;
    const int tid = threadIdx.x;
    const float* sc = predict + (size_t)b * 3 * HWSZ;

    for (int i = tid; i < 2048; i += 1024) hist[i] = 0;
    for (int i = tid; i < HWSZ; i += 1024) { flag[i] = 0; g_pos[b * HWSZ + i] = -1; }
    if (tid < KPAD - KSEL) g_addr[b * KPAD + KSEL + tid] = -1;
    if (tid == 0) s_cnt = 0;
    __syncthreads();

    for (int i = tid; i < HWSZ; i += 1024)
        atomicAdd(&hist[desckey(sc[i]) >> 21], 1);
    __syncthreads();

    if (tid < 64) {
        int s = 0;
        #pragma unroll
        for (int j = 0; j < 32; j++) s += hist[tid * 32 + j];
        partial[tid] = s;
    }
    __syncthreads();
    if (tid == 0) {
        int run = 0;
        for (int t = 0; t < 64; t++) { int v = partial[t]; partial[t] = run; run += v; }
    }
    __syncthreads();
    if (tid < 64) {
        int run = partial[tid];
        #pragma unroll
        for (int j = 0; j < 32; j++) { run += hist[tid * 32 + j]; hist[tid * 32 + j] = run; }
    }
    __syncthreads();

    for (int bin = tid; bin < 2048; bin += 1024) {
        int c = hist[bin];
        int cb = (bin == 0) ? 0 : hist[bin - 1];
        if (c >= KSEL && cb < KSEL) { s_bin = bin; s_before = cb; }
    }
    __syncthreads();
    const int Bb = s_bin;
    const int r = KSEL - s_before;

    for (int i = tid; i < HWSZ; i += 1024) {
        unsigned k = desckey(sc[i]);
        if ((int)(k >> 21) == Bb) {
            int slot = atomicAdd(&s_cnt, 1);
            if (slot < 2048) cand[slot] = (((unsigned long long)k) << 32) | (unsigned)i;
        }
    }
    __syncthreads();
    int cnt = s_cnt; if (cnt > 2048) cnt = 2048;

    if (r >= cnt) {
        // take the whole boundary bin — no sort needed
        for (int j = tid; j < cnt; j += 1024)
            flag[(int)(cand[j] & 0xFFFFFFFFu)] = 1;
    } else {
        int S = 2; while (S < cnt) S <<= 1;     // dynamic sort size
        for (int i = tid; i < S; i += 1024)
            if (i >= cnt) cand[i] = 0xFFFFFFFFFFFFFFFFULL;
        __syncthreads();
        for (int size = 2; size <= S; size <<= 1) {
            for (int stride = size >> 1; stride > 0; stride >>= 1) {
                for (int i = tid; i < S; i += 1024) {
                    int j = i ^ stride;
                    if (j > i) {
                        unsigned long long a = cand[i], c = cand[j];
                        bool up = ((i & size) == 0);
                        if ((a > c) == up) { cand[i] = c; cand[j] = a; }
                    }
                }
                __syncthreads();
            }
        }
        for (int j = tid; j < r; j += 1024)
            flag[(int)(cand[j] & 0xFFFFFFFFu)] = 1;
    }
    __syncthreads();

    const int lo = tid * 8;
    int mycnt = 0;
    #pragma unroll
    for (int q = 0; q < 8; q++) {
        int i = lo + q;
        if (i < HWSZ) {
            int bin = desckey(sc[i]) >> 21;
            if (bin < Bb || flag[i]) mycnt++;
        }
    }
    scanbuf[tid] = mycnt;
    __syncthreads();
    for (int off = 1; off < 1024; off <<= 1) {
        int v = (tid >= off) ? scanbuf[tid - off] : 0;
        __syncthreads();
        scanbuf[tid] += v;
        __syncthreads();
    }
    int pos = scanbuf[tid] - mycnt;
    #pragma unroll
    for (int q = 0; q < 8; q++) {
        int i = lo + q;
        if (i < HWSZ) {
            int bin = desckey(sc[i]) >> 21;
            if (bin < Bb || flag[i]) {
                g_sorted_idx[b * KSEL + pos] = i;
                g_pos[b * HWSZ + i] = pos;
                g_addr[b * KPAD + pos] = (i % HH) * WW + i / HH;
                if (write_idx) out[(size_t)NROWS * ND + b * KSEL + pos] = (float)i;
                pos++;
            }
        }
    }
}

// ---------------- kernel 2: bulk-copy gather + clip + fp16 split ----------------
extern "C" __global__ __launch_bounds__(256)
void gather_kernel(const float* __restrict__ feat) {
    extern __shared__ float sp[];                  // 15000 floats
    __shared__ __align__(8) unsigned long long mbar;
    const int blk = blockIdx.x;
    const int b = blk >> 8, c2 = blk & 255;
    const int tid = threadIdx.x;
    const uint32_t mb = s2u(&mbar);

    if (tid == 0)
        asm volatile("mbarrier.init.shared.b64 [%0], %1;" :: "r"(mb), "r"(1) : "memory");
    __syncthreads();
    if (tid == 0) {
        asm volatile("mbarrier.arrive.expect_tx.shared.b64 _, [%0], %1;"
                     :: "r"(mb), "r"(60000) : "memory");
        const float* src = feat + ((size_t)b * CH + 2 * c2) * HWSZ;
        uint32_t d0 = s2u(sp);
        asm volatile("cp.async.bulk.shared::cluster.global.mbarrier::complete_tx::bytes "
                     "[%0], [%1], %2, [%3];"
                     :: "r"(d0), "l"(src), "r"(30000), "r"(mb) : "memory");
        asm volatile("cp.async.bulk.shared::cluster.global.mbarrier::complete_tx::bytes "
                     "[%0], [%1], %2, [%3];"
                     :: "r"(d0 + 30000), "l"(src + HWSZ), "r"(30000), "r"(mb) : "memory");
    }
    asm volatile(
        "{\n\t.reg .pred P;\n"
        "LW%=:\n\t mbarrier.try_wait.parity.acquire.cta.shared::cta.b64 P, [%0], %1;\n"
        "\t@P bra LD%=;\n\t bra LW%=;\n"
        "LD%=:\n\t}" :: "r"(mb), "r"(0) : "memory");

    const int kb = b * KPAD;
    const size_t oh = ((size_t)b * CPAIRS + c2) * KPAD;
    #pragma unroll
    for (int q = 0; q < 2; q++) {
        int k0 = tid * 8 + q * 4;
        unsigned h[4], l[4];
        #pragma unroll
        for (int j = 0; j < 4; j++) {
            int a = g_addr[kb + k0 + j];
            float v0 = 0.0f, v1 = 0.0f;
            if (a >= 0) {
                v0 = fminf(fmaxf(sp[a], 0.0f), 6.0f);
                v1 = fminf(fmaxf(sp[HWSZ + a], 0.0f), 6.0f);
            }
            h[j] = pack_split_hi(v0, v1);
            l[j] = pack_split_lo(v0, v1);
        }
        *(uint4*)&g_nfh[oh + k0] = make_uint4(h[0], h[1], h[2], h[3]);
        *(uint4*)&g_nfl[oh + k0] = make_uint4(l[0], l[1], l[2], l[3]);
    }
}

// ---------------- MMA / ldmatrix helpers ----------------
#define MMA_F16(acc, a0, a1, a2, a3, b0, b1)                                    \
    asm volatile(                                                               \
        "mma.sync.aligned.m16n8k16.row.col.f32.f16.f16.f32 "                    \
        "{%0,%1,%2,%3}, {%4,%5,%6,%7}, {%8,%9}, {%0,%1,%2,%3};"                 \
        : "+f"(acc[0]), "+f"(acc[1]), "+f"(acc[2]), "+f"(acc[3])                \
        : "r"(a0), "r"(a1), "r"(a2), "r"(a3), "r"(b0), "r"(b1))

#define LDSM_X4(r0, r1, r2, r3, addr)                                           \
    asm volatile("ldmatrix.sync.aligned.m8n8.x4.shared.b16 {%0,%1,%2,%3}, [%4];"\
        : "=r"(r0), "=r"(r1), "=r"(r2), "=r"(r3) : "r"(addr))

// ---------------- gemm core: M64 x N128, ldmatrix fragments ----------------
// As*/Bs* staged per 32-k tile; fragment loads via ldmatrix.x4.
struct GemmSmem {
    unsigned AsH[64 * 20], AsL[64 * 20];
    unsigned BsH[128 * 20], BsL[128 * 20];
};

template <int NKT>   // number of 32-k tiles
__device__ __forceinline__ void gemm_mma_loop(
    GemmSmem& S, int lane, int wm, int wn,
    float acc[2][4][4],
    // staging callbacks are inlined by the callers via lambdas
    void (*dummy)() )
{ /* unused — structure inlined in callers */ }

// ---------------- gemm1: g1 = nf @ w1 ----------------
extern "C" __global__ __launch_bounds__(256, 2)
void gemm1_kernel() {
    __shared__ GemmSmem S;
    const int tid  = threadIdx.x;
    const int lane = tid & 31;
    const int warp = tid >> 5;
    const int wm = (warp & 1) * 32;            // 2 m-warps
    const int wn = (warp >> 1) * 32;           // 4 n-warps
    const int b = blockIdx.x >> 5;             // batch
    const int t = blockIdx.x & 31;             // m-tile (64 rows) within KPAD

    const int c2i = tid & 15;                  // A k2 within tile
    const int m4  = (tid >> 4) * 4;            // A m base
    const int brow = tid >> 1, bkb = (tid & 1) * 8;

    float acc[2][4][4];
    #pragma unroll
    for (int mt = 0; mt < 2; mt++)
        #pragma unroll
        for (int nt = 0; nt < 4; nt++)
            #pragma unroll
            for (int q = 0; q < 4; q++) acc[mt][nt][q] = 0.0f;

    // ldmatrix source addresses (byte offsets added per ks)
    uint32_t aAH[2], aAL[2], bAH[2], bAL[2];
    #pragma unroll
    for (int mt = 0; mt < 2; mt++) {
        int row = wm + mt * 16 + (lane & 15);
        int col = (lane >> 4) << 2;
        aAH[mt] = s2u(&S.AsH[row * 20 + col]);
        aAL[mt] = s2u(&S.AsL[row * 20 + col]);
    }
    #pragma unroll
    for (int p = 0; p < 2; p++) {
        int row = wn + p * 16 + ((lane >> 4) << 3) + (lane & 7);
        int col = ((lane >> 3) & 1) * 4;
        bAH[p] = s2u(&S.BsH[row * 20 + col]);
        bAL[p] = s2u(&S.BsL[row * 20 + col]);
    }

    uint4 ah, al, bh[2], bl[2];
    const size_t abase = (size_t)b * CPAIRS * KPAD + t * 64;

    // preload k-tile 0
    {
        size_t ai = abase + (size_t)c2i * KPAD + m4;
        ah = *(const uint4*)&g_nfh[ai];
        al = *(const uint4*)&g_nfl[ai];
        bh[0] = *(const uint4*)&g_w1h[brow * (CH / 2) + bkb];
        bh[1] = *(const uint4*)&g_w1h[brow * (CH / 2) + bkb + 4];
        bl[0] = *(const uint4*)&g_w1l[brow * (CH / 2) + bkb];
        bl[1] = *(const uint4*)&g_w1l[brow * (CH / 2) + bkb + 4];
    }

    for (int kt = 0; kt < 16; kt++) {
        __syncthreads();
        S.AsH[(m4 + 0) * 20 + c2i] = ah.x;
        S.AsH[(m4 + 1) * 20 + c2i] = ah.y;
        S.AsH[(m4 + 2) * 20 + c2i] = ah.z;
        S.AsH[(m4 + 3) * 20 + c2i] = ah.w;
        S.AsL[(m4 + 0) * 20 + c2i] = al.x;
        S.AsL[(m4 + 1) * 20 + c2i] = al.y;
        S.AsL[(m4 + 2) * 20 + c2i] = al.z;
        S.AsL[(m4 + 3) * 20 + c2i] = al.w;
        {
            int base = brow * 20 + bkb;
            S.BsH[base + 0] = bh[0].x; S.BsH[base + 1] = bh[0].y;
            S.BsH[base + 2] = bh[0].z; S.BsH[base + 3] = bh[0].w;
            S.BsH[base + 4] = bh[1].x; S.BsH[base + 5] = bh[1].y;
            S.BsH[base + 6] = bh[1].z; S.BsH[base + 7] = bh[1].w;
            S.BsL[base + 0] = bl[0].x; S.BsL[base + 1] = bl[0].y;
            S.BsL[base + 2] = bl[0].z; S.BsL[base + 3] = bl[0].w;
            S.BsL[base + 4] = bl[1].x; S.BsL[base + 5] = bl[1].y;
            S.BsL[base + 6] = bl[1].z; S.BsL[base + 7] = bl[1].w;
        }
        __syncthreads();

        if (kt + 1 < 16) {
            size_t an = abase + (size_t)((kt + 1) * 16 + c2i) * KPAD + m4;
            ah = *(const uint4*)&g_nfh[an];
            al = *(const uint4*)&g_nfl[an];
            int k2n = (kt + 1) * 16;
            bh[0] = *(const uint4*)&g_w1h[brow * (CH / 2) + k2n + bkb];
            bh[1] = *(const uint4*)&g_w1h[brow * (CH / 2) + k2n + bkb + 4];
            bl[0] = *(const uint4*)&g_w1l[brow * (CH / 2) + k2n + bkb];
            bl[1] = *(const uint4*)&g_w1l[brow * (CH / 2) + k2n + bkb + 4];
        }

        #pragma unroll
        for (int ks = 0; ks < 2; ks++) {
            const uint32_t off = ks * 32;       // 8 words
            unsigned aH[2][4], aL[2][4], bHf[4][2], bLf[4][2];
            #pragma unroll
            for (int mt = 0; mt < 2; mt++) {
                LDSM_X4(aH[mt][0], aH[mt][1], aH[mt][2], aH[mt][3], aAH[mt] + off);
                LDSM_X4(aL[mt][0], aL[mt][1], aL[mt][2], aL[mt][3], aAL[mt] + off);
            }
            #pragma unroll
            for (int p = 0; p < 2; p++) {
                LDSM_X4(bHf[2*p][0], bHf[2*p][1], bHf[2*p+1][0], bHf[2*p+1][1], bAH[p] + off);
                LDSM_X4(bLf[2*p][0], bLf[2*p][1], bLf[2*p+1][0], bLf[2*p+1][1], bAL[p] + off);
            }
            #pragma unroll
            for (int mt = 0; mt < 2; mt++)
                #pragma unroll
                for (int nt = 0; nt < 4; nt++) {
                    MMA_F16(acc[mt][nt], aL[mt][0], aL[mt][1], aL[mt][2], aL[mt][3],
                            bHf[nt][0], bHf[nt][1]);
                    MMA_F16(acc[mt][nt], aH[mt][0], aH[mt][1], aH[mt][2], aH[mt][3],
                            bLf[nt][0], bLf[nt][1]);
                    MMA_F16(acc[mt][nt], aH[mt][0], aH[mt][1], aH[mt][2], aH[mt][3],
                            bHf[nt][0], bHf[nt][1]);
                }
        }
    }

    #pragma unroll
    for (int mt = 0; mt < 2; mt++) {
        int rk = t * 64 + wm + mt * 16 + (lane >> 2);
        int colb = (lane & 3) * 2;
        #pragma unroll
        for (int nt = 0; nt < 4; nt++) {
            int col = wn + nt * 8 + colb;
            if (rk < KSEL)
                *(float2*)&g_g1[(size_t)(b * KSEL + rk) * ND + col] =
                    make_float2(acc[mt][nt][0], acc[mt][nt][1]);
            if (rk + 8 < KSEL)
                *(float2*)&g_g1[(size_t)(b * KSEL + rk + 8) * ND + col] =
                    make_float2(acc[mt][nt][2], acc[mt][nt][3]);
        }
    }
}

// ---------------- gemm2: g2 = x1 @ w2 ----------------
extern "C" __global__ __launch_bounds__(256, 2)
void gemm2_kernel() {
    __shared__ GemmSmem S;
    const int tid  = threadIdx.x;
    const int lane = tid & 31;
    const int warp = tid >> 5;
    const int wm = (warp & 1) * 32;
    const int wn = (warp >> 1) * 32;
    const int gm = blockIdx.x * 64;
    const int K2 = ND / 2;

    const int arow = tid >> 2, aq = tid & 3;   // A: row 0..63, quarter
    const int brow = tid >> 1, bkb = (tid & 1) * 8;

    float acc[2][4][4];
    #pragma unroll
    for (int mt = 0; mt < 2; mt++)
        #pragma unroll
        for (int nt = 0; nt < 4; nt++)
            #pragma unroll
            for (int q = 0; q < 4; q++) acc[mt][nt][q] = 0.0f;

    uint32_t aAH[2], aAL[2], bAH[2], bAL[2];
    #pragma unroll
    for (int mt = 0; mt < 2; mt++) {
        int row = wm + mt * 16 + (lane & 15);
        int col = (lane >> 4) << 2;
        aAH[mt] = s2u(&S.AsH[row * 20 + col]);
        aAL[mt] = s2u(&S.AsL[row * 20 + col]);
    }
    #pragma unroll
    for (int p = 0; p < 2; p++) {
        int row = wn + p * 16 + ((lane >> 4) << 3) + (lane & 7);
        int col = ((lane >> 3) & 1) * 4;
        bAH[p] = s2u(&S.BsH[row * 20 + col]);
        bAL[p] = s2u(&S.BsL[row * 20 + col]);
    }

    float v[8];
    uint4 bh[2], bl[2];
    {
        #pragma unroll
        for (int q = 0; q < 2; q++) {
            float4 tv = *(const float4*)&g_x1[(size_t)(gm + arow) * ND + aq * 8 + q * 4];
            v[q * 4] = tv.x; v[q * 4 + 1] = tv.y; v[q * 4 + 2] = tv.z; v[q * 4 + 3] = tv.w;
        }
        bh[0] = *(const uint4*)&g_w2h[brow * K2 + bkb];
        bh[1] = *(const uint4*)&g_w2h[brow * K2 + bkb + 4];
        bl[0] = *(const uint4*)&g_w2l[brow * K2 + bkb];
        bl[1] = *(const uint4*)&g_w2l[brow * K2 + bkb + 4];
    }

    for (int kt = 0; kt < 4; kt++) {
        __syncthreads();
        #pragma unroll
        for (int j = 0; j < 4; j++) {
            int kidx = arow * 20 + aq * 4 + j;
            S.AsH[kidx] = pack_split_hi(v[2 * j], v[2 * j + 1]);
            S.AsL[kidx] = pack_split_lo(v[2 * j], v[2 * j + 1]);
        }
        {
            int base = brow * 20 + bkb;
            S.BsH[base + 0] = bh[0].x; S.BsH[base + 1] = bh[0].y;
            S.BsH[base + 2] = bh[0].z; S.BsH[base + 3] = bh[0].w;
            S.BsH[base + 4] = bh[1].x; S.BsH[base + 5] = bh[1].y;
            S.BsH[base + 6] = bh[1].z; S.BsH[base + 7] = bh[1].w;
            S.BsL[base + 0] = bl[0].x; S.BsL[base + 1] = bl[0].y;
            S.BsL[base + 2] = bl[0].z; S.BsL[base + 3] = bl[0].w;
            S.BsL[base + 4] = bl[1].x; S.BsL[base + 5] = bl[1].y;
            S.BsL[base + 6] = bl[1].z; S.BsL[base + 7] = bl[1].w;
        }
        __syncthreads();

        if (kt + 1 < 4) {
            int cb = (kt + 1) * 32 + aq * 8;
            #pragma unroll
            for (int q = 0; q < 2; q++) {
                float4 tv = *(const float4*)&g_x1[(size_t)(gm + arow) * ND + cb + q * 4];
                v[q * 4] = tv.x; v[q * 4 + 1] = tv.y; v[q * 4 + 2] = tv.z; v[q * 4 + 3] = tv.w;
            }
            int k2n = (kt + 1) * 16;
            bh[0] = *(const uint4*)&g_w2h[brow * K2 + k2n + bkb];
            bh[1] = *(const uint4*)&g_w2h[brow * K2 + k2n + bkb + 4];
            bl[0] = *(const uint4*)&g_w2l[brow * K2 + k2n + bkb];
            bl[1] = *(const uint4*)&g_w2l[brow * K2 + k2n + bkb + 4];
        }

        #pragma unroll
        for (int ks = 0; ks < 2; ks++) {
            const uint32_t off = ks * 32;
            unsigned aH[2][4], aL[2][4], bHf[4][2], bLf[4][2];
            #pragma unroll
            for (int mt = 0; mt < 2; mt++) {
                LDSM_X4(aH[mt][0], aH[mt][1], aH[mt][2], aH[mt][3], aAH[mt] + off);
                LDSM_X4(aL[mt][0], aL[mt][1], aL[mt][2], aL[mt][3], aAL[mt] + off);
            }
            #pragma unroll
            for (int p = 0; p < 2; p++) {
                LDSM_X4(bHf[2*p][0], bHf[2*p][1], bHf[2*p+1][0], bHf[2*p+1][1], bAH[p] + off);
                LDSM_X4(bLf[2*p][0], bLf[2*p][1], bLf[2*p+1][0], bLf[2*p+1][1], bAL[p] + off);
            }
            #pragma unroll
            for (int mt = 0; mt < 2; mt++)
                #pragma unroll
                for (int nt = 0; nt < 4; nt++) {
                    MMA_F16(acc[mt][nt], aL[mt][0], aL[mt][1], aL[mt][2], aL[mt][3],
                            bHf[nt][0], bHf[nt][1]);
                    MMA_F16(acc[mt][nt], aH[mt][0], aH[mt][1], aH[mt][2], aH[mt][3],
                            bLf[nt][0], bLf[nt][1]);
                    MMA_F16(acc[mt][nt], aH[mt][0], aH[mt][1], aH[mt][2], aH[mt][3],
                            bHf[nt][0], bHf[nt][1]);
                }
        }
    }

    #pragma unroll
    for (int mt = 0; mt < 2; mt++) {
        int row0 = gm + wm + mt * 16 + (lane >> 2);
        int colb = (lane & 3) * 2;
        #pragma unroll
        for (int nt = 0; nt < 4; nt++) {
            int col = wn + nt * 8 + colb;
            *(float2*)&g_g2[(size_t)row0 * ND + col] =
                make_float2(acc[mt][nt][0], acc[mt][nt][1]);
            *(float2*)&g_g2[(size_t)(row0 + 8) * ND + col] =
                make_float2(acc[mt][nt][2], acc[mt][nt][3]);
        }
    }
}

// ---------------- sparse 3x3 neighbor sums ----------------
extern "C" __global__ __launch_bounds__(256)
void nsum1_kernel(const float* __restrict__ b1) {
    const int row = blockIdx.x * 8 + (threadIdx.x >> 5);
    const int lane = threadIdx.x & 31;
    const int b = row / KSEL, k = row - b * KSEL;
    const int i = g_sorted_idx[row];
    const int py = i / WW, px = i % WW;
    int nb = -1;
    if (lane < 9) {
        int ny = py + lane / 3 - 1, nx = px + lane % 3 - 1;
        if ((unsigned)ny < HH && (unsigned)nx < WW)
            nb = g_pos[b * HWSZ + ny * WW + nx];
    }
    float4 acc = *(const float4*)&b1[(size_t)k * ND + lane * 4];
    #pragma unroll
    for (int j = 0; j < 9; j++) {
        int n = __shfl_sync(0xFFFFFFFFu, nb, j);
        if (n >= 0) {
            float4 v = *(const float4*)&g_g1[(size_t)(b * KSEL + n) * ND + lane * 4];
            acc.x += v.x; acc.y += v.y; acc.z += v.z; acc.w += v.w;
        }
    }
    *(float4*)&g_x1[(size_t)row * ND + lane * 4] = acc;
}

extern "C" __global__ __launch_bounds__(256)
void final_kernel(const float* __restrict__ b2, float* __restrict__ out) {
    const int row = blockIdx.x * 8 + (threadIdx.x >> 5);
    const int lane = threadIdx.x & 31;
    const int b = row / KSEL, k = row - b * KSEL;
    const int i = g_sorted_idx[row];
    const int py = i / WW, px = i % WW;
    int nb = -1;
    if (lane < 9) {
        int ny = py + lane / 3 - 1, nx = px + lane % 3 - 1;
        if ((unsigned)ny < HH && (unsigned)nx < WW)
            nb = g_pos[b * HWSZ + ny * WW + nx];
    }
    float4 acc = *(const float4*)&b2[(size_t)k * ND + lane * 4];
    float4 x1v = *(const float4*)&g_x1[(size_t)row * ND + lane * 4];
    acc.x += x1v.x; acc.y += x1v.y; acc.z += x1v.z; acc.w += x1v.w;
    #pragma unroll
    for (int j = 0; j < 9; j++) {
        int n = __shfl_sync(0xFFFFFFFFu, nb, j);
        if (n >= 0) {
            float4 v = *(const float4*)&g_g2[(size_t)(b * KSEL + n) * ND + lane * 4];
            acc.x += v.x; acc.y += v.y; acc.z += v.z; acc.w += v.w;
        }
    }
    float4 o = make_float4(tanhf(acc.x), tanhf(acc.y), tanhf(acc.z), tanhf(acc.w));
    *(float4*)&out[(size_t)row * ND + lane * 4] = o;
}

// ---------------- launch ----------------
extern "C" void kernel_launch(void* const* d_in, const int* in_sizes, int n_in,
                              void* d_out, int out_size) {
    const float* feat = (const float*)d_in[0];
    const float* pred = (const float*)d_in[1];
    const float* w1   = (const float*)d_in[2];
    const float* b1   = (const float*)d_in[3];
    const float* w2   = (const float*)d_in[4];
    const float* b2   = (const float*)d_in[5];
    float* out = (float*)d_out;

    const int feat_elems = NROWS * ND;
    const int write_idx = (out_size >= feat_elems + NROWS) ? 1 : 0;

    cudaFuncSetAttribute((const void*)gather_kernel,
                         cudaFuncAttributeMaxDynamicSharedMemorySize, 60000);

    prep_kernel<<<(ND * (CH / 2) + ND * (ND / 2) + 255) / 256, 256>>>(w1, w2);
    topk_kernel<<<NB, 1024>>>(pred, out, write_idx);
    gather_kernel<<<NB * CPAIRS, 256, 60000>>>(feat);
    gemm1_kernel<<<NB * 32, 256>>>();          // 256 CTAs, M64 tiles
    nsum1_kernel<<<NROWS / 8, 256>>>(b1);
    gemm2_kernel<<<NROWS / 64, 256>>>();       // 250 CTAs
    final_kernel<<<NROWS / 8, 256>>>(b2, out);
}

// round 9
// speedup vs baseline: 2.2942x; 1.0608x over previous
#include <cuda_runtime.h>
#include <cuda_fp16.h>
#include <stdint.h>
#include <math.h>

#define KSEL 2000
#define HH 75
#define WW 100
#define HWSZ 7500
#define NB 8
#define CH 512
#define ND 128
#define NROWS (NB * KSEL)
#define CPAIRS (CH / 2)     // 256
#define KPAD 2048           // per-batch padded row count
#define SST 20              // smem row stride (words); 80B rows => ldmatrix-aligned

// ---------------- scratch (static device allocations) ----------------
__device__ int      g_sorted_idx[NROWS];
__device__ int      g_pos[NB * HWSZ];
__device__ int      g_addr[NB * KPAD];
__device__ unsigned g_nfh[(size_t)NB * CPAIRS * KPAD];  // A hi half2 [b][c2][k]
__device__ unsigned g_nfl[(size_t)NB * CPAIRS * KPAD];  // A lo half2
__device__ float    g_g1[NROWS * ND];
__device__ float    g_x1[NROWS * ND];
__device__ float    g_g2[NROWS * ND];
__device__ unsigned g_w1h[ND * (CH / 2)];               // [n][k2]
__device__ unsigned g_w1l[ND * (CH / 2)];
__device__ unsigned g_w2h[ND * (ND / 2)];
__device__ unsigned g_w2l[ND * (ND / 2)];

__device__ __forceinline__ unsigned desckey(float f) {
    unsigned u = __float_as_uint(f);
    unsigned ord = (u & 0x80000000u) ? ~u : (u ^ 0x80000000u);
    return ~ord;
}
__device__ __forceinline__ unsigned pack_split_hi(float v0, float v1) {
    __half h0 = __float2half_rn(v0), h1 = __float2half_rn(v1);
    return (unsigned)__half_as_ushort(h0) | ((unsigned)__half_as_ushort(h1) << 16);
}
__device__ __forceinline__ unsigned pack_split_lo(float v0, float v1) {
    __half h0 = __float2half_rn(v0), h1 = __float2half_rn(v1);
    __half l0 = __float2half_rn(v0 - __half2float(h0));
    __half l1 = __float2half_rn(v1 - __half2float(h1));
    return (unsigned)__half_as_ushort(l0) | ((unsigned)__half_as_ushort(l1) << 16);
}
__device__ __forceinline__ uint32_t s2u(const void* p) {
    return (uint32_t)__cvta_generic_to_shared(p);
}

// ---------------- weight split prep ----------------
extern "C" __global__ __launch_bounds__(256)
void prep_kernel(const float* __restrict__ w1, const float* __restrict__ w2) {
    int idx = blockIdx.x * 256 + threadIdx.x;
    const int N1 = ND * (CH / 2);
    if (idx < N1) {
        int f = idx % ND, c2 = idx / ND;
        float v0 = w1[(2 * c2) * ND + f], v1 = w1[(2 * c2 + 1) * ND + f];
        g_w1h[f * (CH / 2) + c2] = pack_split_hi(v0, v1);
        g_w1l[f * (CH / 2) + c2] = pack_split_lo(v0, v1);
    } else {
        int j = idx - N1;
        if (j < ND * (ND / 2)) {
            int f = j % ND, c2 = j / ND;
            float v0 = w2[(2 * c2) * ND + f], v1 = w2[(2 * c2 + 1) * ND + f];
            g_w2h[f * (ND / 2) + c2] = pack_split_hi(v0, v1);
            g_w2l[f * (ND / 2) + c2] = pack_split_lo(v0, v1);
        }
    }
}

// ---------------- kernel 1: per-batch exact top-K via radix histogram ----------------
extern "C" __global__ __launch_bounds__(1024)
void topk_kernel(const float* __restrict__ predict, float* __restrict__ out, int write_idx) {
    __shared__ int hist[2048];
    __shared__ int partial[64];
    __shared__ unsigned long long cand[2048];
    __shared__ unsigned char flag[HWSZ];
    __shared__ int scanbuf[1024];
    __shared__ int s_bin, s_before, s_cnt;

    const int b = blockIdx.x;
    const int tid = threadIdx.x;
    const float* sc = predict + (size_t)b * 3 * HWSZ;

    for (int i = tid; i < 2048; i += 1024) hist[i] = 0;
    for (int i = tid; i < HWSZ; i += 1024) { flag[i] = 0; g_pos[b * HWSZ + i] = -1; }
    if (tid < KPAD - KSEL) g_addr[b * KPAD + KSEL + tid] = -1;
    if (tid == 0) s_cnt = 0;
    __syncthreads();

    for (int i = tid; i < HWSZ; i += 1024)
        atomicAdd(&hist[desckey(sc[i]) >> 21], 1);
    __syncthreads();

    if (tid < 64) {
        int s = 0;
        #pragma unroll
        for (int j = 0; j < 32; j++) s += hist[tid * 32 + j];
        partial[tid] = s;
    }
    __syncthreads();
    if (tid == 0) {
        int run = 0;
        for (int t = 0; t < 64; t++) { int v = partial[t]; partial[t] = run; run += v; }
    }
    __syncthreads();
    if (tid < 64) {
        int run = partial[tid];
        #pragma unroll
        for (int j = 0; j < 32; j++) { run += hist[tid * 32 + j]; hist[tid * 32 + j] = run; }
    }
    __syncthreads();

    for (int bin = tid; bin < 2048; bin += 1024) {
        int c = hist[bin];
        int cb = (bin == 0) ? 0 : hist[bin - 1];
        if (c >= KSEL && cb < KSEL) { s_bin = bin; s_before = cb; }
    }
    __syncthreads();
    const int Bb = s_bin;
    const int r = KSEL - s_before;

    for (int i = tid; i < HWSZ; i += 1024) {
        unsigned k = desckey(sc[i]);
        if ((int)(k >> 21) == Bb) {
            int slot = atomicAdd(&s_cnt, 1);
            if (slot < 2048) cand[slot] = (((unsigned long long)k) << 32) | (unsigned)i;
        }
    }
    __syncthreads();
    int cnt = s_cnt; if (cnt > 2048) cnt = 2048;

    if (r >= cnt) {
        for (int j = tid; j < cnt; j += 1024)
            flag[(int)(cand[j] & 0xFFFFFFFFu)] = 1;
    } else {
        int S = 2; while (S < cnt) S <<= 1;
        for (int i = tid; i < S; i += 1024)
            if (i >= cnt) cand[i] = 0xFFFFFFFFFFFFFFFFULL;
        __syncthreads();
        for (int size = 2; size <= S; size <<= 1) {
            for (int stride = size >> 1; stride > 0; stride >>= 1) {
                for (int i = tid; i < S; i += 1024) {
                    int j = i ^ stride;
                    if (j > i) {
                        unsigned long long a = cand[i], c = cand[j];
                        bool up = ((i & size) == 0);
                        if ((a > c) == up) { cand[i] = c; cand[j] = a; }
                    }
                }
                __syncthreads();
            }
        }
        for (int j = tid; j < r; j += 1024)
            flag[(int)(cand[j] & 0xFFFFFFFFu)] = 1;
    }
    __syncthreads();

    const int lo = tid * 8;
    int mycnt = 0;
    #pragma unroll
    for (int q = 0; q < 8; q++) {
        int i = lo + q;
        if (i < HWSZ) {
            int bin = desckey(sc[i]) >> 21;
            if (bin < Bb || flag[i]) mycnt++;
        }
    }
    scanbuf[tid] = mycnt;
    __syncthreads();
    for (int off = 1; off < 1024; off <<= 1) {
        int v = (tid >= off) ? scanbuf[tid - off] : 0;
        __syncthreads();
        scanbuf[tid] += v;
        __syncthreads();
    }
    int pos = scanbuf[tid] - mycnt;
    #pragma unroll
    for (int q = 0; q < 8; q++) {
        int i = lo + q;
        if (i < HWSZ) {
            int bin = desckey(sc[i]) >> 21;
            if (bin < Bb || flag[i]) {
                g_sorted_idx[b * KSEL + pos] = i;
                g_pos[b * HWSZ + i] = pos;
                g_addr[b * KPAD + pos] = (i % HH) * WW + i / HH;
                if (write_idx) out[(size_t)NROWS * ND + b * KSEL + pos] = (float)i;
                pos++;
            }
        }
    }
}

// ---------------- kernel 2: bulk-copy gather + clip + fp16 split ----------------
extern "C" __global__ __launch_bounds__(256)
void gather_kernel(const float* __restrict__ feat) {
    extern __shared__ float sp[];                  // 15000 floats
    __shared__ __align__(8) unsigned long long mbar;
    const int blk = blockIdx.x;
    const int b = blk >> 8, c2 = blk & 255;
    const int tid = threadIdx.x;
    const uint32_t mb = s2u(&mbar);

    if (tid == 0)
        asm volatile("mbarrier.init.shared.b64 [%0], %1;" :: "r"(mb), "r"(1) : "memory");
    __syncthreads();
    if (tid == 0) {
        asm volatile("mbarrier.arrive.expect_tx.shared.b64 _, [%0], %1;"
                     :: "r"(mb), "r"(60000) : "memory");
        const float* src = feat + ((size_t)b * CH + 2 * c2) * HWSZ;
        uint32_t d0 = s2u(sp);
        asm volatile("cp.async.bulk.shared::cluster.global.mbarrier::complete_tx::bytes "
                     "[%0], [%1], %2, [%3];"
                     :: "r"(d0), "l"(src), "r"(30000), "r"(mb) : "memory");
        asm volatile("cp.async.bulk.shared::cluster.global.mbarrier::complete_tx::bytes "
                     "[%0], [%1], %2, [%3];"
                     :: "r"(d0 + 30000), "l"(src + HWSZ), "r"(30000), "r"(mb) : "memory");
    }
    asm volatile(
        "{\n\t.reg .pred P;\n"
        "LW%=:\n\t mbarrier.try_wait.parity.acquire.cta.shared::cta.b64 P, [%0], %1;\n"
        "\t@P bra LD%=;\n\t bra LW%=;\n"
        "LD%=:\n\t}" :: "r"(mb), "r"(0) : "memory");

    const int kb = b * KPAD;
    const size_t oh = ((size_t)b * CPAIRS + c2) * KPAD;
    #pragma unroll
    for (int q = 0; q < 2; q++) {
        int k0 = tid * 8 + q * 4;
        unsigned h[4], l[4];
        #pragma unroll
        for (int j = 0; j < 4; j++) {
            int a = g_addr[kb + k0 + j];
            float v0 = 0.0f, v1 = 0.0f;
            if (a >= 0) {
                v0 = fminf(fmaxf(sp[a], 0.0f), 6.0f);
                v1 = fminf(fmaxf(sp[HWSZ + a], 0.0f), 6.0f);
            }
            h[j] = pack_split_hi(v0, v1);
            l[j] = pack_split_lo(v0, v1);
        }
        *(uint4*)&g_nfh[oh + k0] = make_uint4(h[0], h[1], h[2], h[3]);
        *(uint4*)&g_nfl[oh + k0] = make_uint4(l[0], l[1], l[2], l[3]);
    }
}

// ---------------- MMA / ldmatrix helpers ----------------
#define MMA_F16(acc, a0, a1, a2, a3, b0, b1)                                    \
    asm volatile(                                                               \
        "mma.sync.aligned.m16n8k16.row.col.f32.f16.f16.f32 "                    \
        "{%0,%1,%2,%3}, {%4,%5,%6,%7}, {%8,%9}, {%0,%1,%2,%3};"                 \
        : "+f"(acc[0]), "+f"(acc[1]), "+f"(acc[2]), "+f"(acc[3])                \
        : "r"(a0), "r"(a1), "r"(a2), "r"(a3), "r"(b0), "r"(b1))

#define LDSM_X4(r0, r1, r2, r3, addr)                                           \
    asm volatile("ldmatrix.sync.aligned.m8n8.x4.shared.b16 {%0,%1,%2,%3}, [%4];"\
        : "=r"(r0), "=r"(r1), "=r"(r2), "=r"(r3) : "r"(addr))

struct GemmSmem {
    unsigned AsH[64 * SST], AsL[64 * SST];
    unsigned BsH[128 * SST], BsL[128 * SST];
};

// A-tile swizzle: word (m, c2) -> m*SST + ((c2>>2) ^ ((m>>3)&3))*4 + (c2&3)
__device__ __forceinline__ int aswz(int m, int c2) {
    return m * SST + ((((c2 >> 2) ^ ((m >> 3) & 3)) << 2) | (c2 & 3));
}

// ---------------- gemm1: g1 = nf @ w1 ----------------
extern "C" __global__ __launch_bounds__(256, 2)
void gemm1_kernel() {
    __shared__ GemmSmem S;
    const int tid  = threadIdx.x;
    const int lane = tid & 31;
    const int warp = tid >> 5;
    const int wm = (warp & 1) * 32;            // 2 m-warps
    const int wn = (warp >> 1) * 32;           // 4 n-warps
    const int b = blockIdx.x >> 5;             // batch
    const int t = blockIdx.x & 31;             // m-tile (64 rows)

    // COALESCED A mapping: lanes walk m (contiguous k-major rows)
    const int c2i = tid >> 4;                  // 0..15 channel-pair in tile
    const int m4  = (tid & 15) * 4;            // m base
    const int brow = tid >> 1, bkb = (tid & 1) * 8;

    float acc[2][4][4];
    #pragma unroll
    for (int mt = 0; mt < 2; mt++)
        #pragma unroll
        for (int nt = 0; nt < 4; nt++)
            #pragma unroll
            for (int q = 0; q < 4; q++) acc[mt][nt][q] = 0.0f;

    // A store swizzled word column (constant per thread; (m4+j)>>3 == m4>>3 for j<4)
    const int asw0 = aswz(m4 + 0, c2i);
    const int asw1 = aswz(m4 + 1, c2i);
    const int asw2 = aswz(m4 + 2, c2i);
    const int asw3 = aswz(m4 + 3, c2i);

    // A ldmatrix addresses per [mt][ks] (swizzle breaks constant ks offset)
    uint32_t aAH[2][2], aAL[2][2], bAH[2], bAL[2];
    #pragma unroll
    for (int mt = 0; mt < 2; mt++) {
        int row = wm + mt * 16 + (lane & 15);
        #pragma unroll
        for (int ks = 0; ks < 2; ks++) {
            int unit = (lane >> 4) + 2 * ks;           // 0..3
            int su = unit ^ ((row >> 3) & 3);
            aAH[mt][ks] = s2u(&S.AsH[row * SST + su * 4]);
            aAL[mt][ks] = s2u(&S.AsL[row * SST + su * 4]);
        }
    }
    #pragma unroll
    for (int p = 0; p < 2; p++) {
        int row = wn + p * 16 + ((lane >> 4) << 3) + (lane & 7);
        int col = ((lane >> 3) & 1) * 4;
        bAH[p] = s2u(&S.BsH[row * SST + col]);
        bAL[p] = s2u(&S.BsL[row * SST + col]);
    }

    uint4 ah, al, bh[2], bl[2];
    const size_t abase = (size_t)b * CPAIRS * KPAD + t * 64;

    {
        size_t ai = abase + (size_t)c2i * KPAD + m4;
        ah = *(const uint4*)&g_nfh[ai];
        al = *(const uint4*)&g_nfl[ai];
        bh[0] = *(const uint4*)&g_w1h[brow * (CH / 2) + bkb];
        bh[1] = *(const uint4*)&g_w1h[brow * (CH / 2) + bkb + 4];
        bl[0] = *(const uint4*)&g_w1l[brow * (CH / 2) + bkb];
        bl[1] = *(const uint4*)&g_w1l[brow * (CH / 2) + bkb + 4];
    }

    for (int kt = 0; kt < 16; kt++) {
        __syncthreads();
        S.AsH[asw0] = ah.x; S.AsH[asw1] = ah.y;
        S.AsH[asw2] = ah.z; S.AsH[asw3] = ah.w;
        S.AsL[asw0] = al.x; S.AsL[asw1] = al.y;
        S.AsL[asw2] = al.z; S.AsL[asw3] = al.w;
        {
            int base = brow * SST + bkb;
            S.BsH[base + 0] = bh[0].x; S.BsH[base + 1] = bh[0].y;
            S.BsH[base + 2] = bh[0].z; S.BsH[base + 3] = bh[0].w;
            S.BsH[base + 4] = bh[1].x; S.BsH[base + 5] = bh[1].y;
            S.BsH[base + 6] = bh[1].z; S.BsH[base + 7] = bh[1].w;
            S.BsL[base + 0] = bl[0].x; S.BsL[base + 1] = bl[0].y;
            S.BsL[base + 2] = bl[0].z; S.BsL[base + 3] = bl[0].w;
            S.BsL[base + 4] = bl[1].x; S.BsL[base + 5] = bl[1].y;
            S.BsL[base + 6] = bl[1].z; S.BsL[base + 7] = bl[1].w;
        }
        __syncthreads();

        if (kt + 1 < 16) {
            size_t an = abase + (size_t)((kt + 1) * 16 + c2i) * KPAD + m4;
            ah = *(const uint4*)&g_nfh[an];
            al = *(const uint4*)&g_nfl[an];
            int k2n = (kt + 1) * 16;
            bh[0] = *(const uint4*)&g_w1h[brow * (CH / 2) + k2n + bkb];
            bh[1] = *(const uint4*)&g_w1h[brow * (CH / 2) + k2n + bkb + 4];
            bl[0] = *(const uint4*)&g_w1l[brow * (CH / 2) + k2n + bkb];
            bl[1] = *(const uint4*)&g_w1l[brow * (CH / 2) + k2n + bkb + 4];
        }

        #pragma unroll
        for (int ks = 0; ks < 2; ks++) {
            const uint32_t off = ks * 32;       // B only (A uses per-ks addrs)
            unsigned aH[2][4], aL[2][4], bHf[4][2], bLf[4][2];
            #pragma unroll
            for (int mt = 0; mt < 2; mt++) {
                LDSM_X4(aH[mt][0], aH[mt][1], aH[mt][2], aH[mt][3], aAH[mt][ks]);
                LDSM_X4(aL[mt][0], aL[mt][1], aL[mt][2], aL[mt][3], aAL[mt][ks]);
            }
            #pragma unroll
            for (int p = 0; p < 2; p++) {
                LDSM_X4(bHf[2*p][0], bHf[2*p][1], bHf[2*p+1][0], bHf[2*p+1][1], bAH[p] + off);
                LDSM_X4(bLf[2*p][0], bLf[2*p][1], bLf[2*p+1][0], bLf[2*p+1][1], bAL[p] + off);
            }
            #pragma unroll
            for (int mt = 0; mt < 2; mt++)
                #pragma unroll
                for (int nt = 0; nt < 4; nt++) {
                    MMA_F16(acc[mt][nt], aL[mt][0], aL[mt][1], aL[mt][2], aL[mt][3],
                            bHf[nt][0], bHf[nt][1]);
                    MMA_F16(acc[mt][nt], aH[mt][0], aH[mt][1], aH[mt][2], aH[mt][3],
                            bLf[nt][0], bLf[nt][1]);
                    MMA_F16(acc[mt][nt], aH[mt][0], aH[mt][1], aH[mt][2], aH[mt][3],
                            bHf[nt][0], bHf[nt][1]);
                }
        }
    }

    #pragma unroll
    for (int mt = 0; mt < 2; mt++) {
        int rk = t * 64 + wm + mt * 16 + (lane >> 2);
        int colb = (lane & 3) * 2;
        #pragma unroll
        for (int nt = 0; nt < 4; nt++) {
            int col = wn + nt * 8 + colb;
            if (rk < KSEL)
                *(float2*)&g_g1[(size_t)(b * KSEL + rk) * ND + col] =
                    make_float2(acc[mt][nt][0], acc[mt][nt][1]);
            if (rk + 8 < KSEL)
                *(float2*)&g_g1[(size_t)(b * KSEL + rk + 8) * ND + col] =
                    make_float2(acc[mt][nt][2], acc[mt][nt][3]);
        }
    }
}

// ---------------- gemm2: g2 = x1 @ w2 ----------------
extern "C" __global__ __launch_bounds__(256, 2)
void gemm2_kernel() {
    __shared__ GemmSmem S;
    const int tid  = threadIdx.x;
    const int lane = tid & 31;
    const int warp = tid >> 5;
    const int wm = (warp & 1) * 32;
    const int wn = (warp >> 1) * 32;
    const int gm = blockIdx.x * 64;
    const int K2 = ND / 2;

    const int arow = tid >> 2, aq = tid & 3;
    const int brow = tid >> 1, bkb = (tid & 1) * 8;

    float acc[2][4][4];
    #pragma unroll
    for (int mt = 0; mt < 2; mt++)
        #pragma unroll
        for (int nt = 0; nt < 4; nt++)
            #pragma unroll
            for (int q = 0; q < 4; q++) acc[mt][nt][q] = 0.0f;

    uint32_t aAH[2], aAL[2], bAH[2], bAL[2];
    #pragma unroll
    for (int mt = 0; mt < 2; mt++) {
        int row = wm + mt * 16 + (lane & 15);
        int col = (lane >> 4) << 2;
        aAH[mt] = s2u(&S.AsH[row * SST + col]);
        aAL[mt] = s2u(&S.AsL[row * SST + col]);
    }
    #pragma unroll
    for (int p = 0; p < 2; p++) {
        int row = wn + p * 16 + ((lane >> 4) << 3) + (lane & 7);
        int col = ((lane >> 3) & 1) * 4;
        bAH[p] = s2u(&S.BsH[row * SST + col]);
        bAL[p] = s2u(&S.BsL[row * SST + col]);
    }

    float v[8];
    uint4 bh[2], bl[2];
    {
        #pragma unroll
        for (int q = 0; q < 2; q++) {
            float4 tv = *(const float4*)&g_x1[(size_t)(gm + arow) * ND + aq * 8 + q * 4];
            v[q * 4] = tv.x; v[q * 4 + 1] = tv.y; v[q * 4 + 2] = tv.z; v[q * 4 + 3] = tv.w;
        }
        bh[0] = *(const uint4*)&g_w2h[brow * K2 + bkb];
        bh[1] = *(const uint4*)&g_w2h[brow * K2 + bkb + 4];
        bl[0] = *(const uint4*)&g_w2l[brow * K2 + bkb];
        bl[1] = *(const uint4*)&g_w2l[brow * K2 + bkb + 4];
    }

    for (int kt = 0; kt < 4; kt++) {
        __syncthreads();
        #pragma unroll
        for (int j = 0; j < 4; j++) {
            int kidx = arow * SST + aq * 4 + j;
            S.AsH[kidx] = pack_split_hi(v[2 * j], v[2 * j + 1]);
            S.AsL[kidx] = pack_split_lo(v[2 * j], v[2 * j + 1]);
        }
        {
            int base = brow * SST + bkb;
            S.BsH[base + 0] = bh[0].x; S.BsH[base + 1] = bh[0].y;
            S.BsH[base + 2] = bh[0].z; S.BsH[base + 3] = bh[0].w;
            S.BsH[base + 4] = bh[1].x; S.BsH[base + 5] = bh[1].y;
            S.BsH[base + 6] = bh[1].z; S.BsH[base + 7] = bh[1].w;
            S.BsL[base + 0] = bl[0].x; S.BsL[base + 1] = bl[0].y;
            S.BsL[base + 2] = bl[0].z; S.BsL[base + 3] = bl[0].w;
            S.BsL[base + 4] = bl[1].x; S.BsL[base + 5] = bl[1].y;
            S.BsL[base + 6] = bl[1].z; S.BsL[base + 7] = bl[1].w;
        }
        __syncthreads();

        if (kt + 1 < 4) {
            int cb = (kt + 1) * 32 + aq * 8;
            #pragma unroll
            for (int q = 0; q < 2; q++) {
                float4 tv = *(const float4*)&g_x1[(size_t)(gm + arow) * ND + cb + q * 4];
                v[q * 4] = tv.x; v[q * 4 + 1] = tv.y; v[q * 4 + 2] = tv.z; v[q * 4 + 3] = tv.w;
            }
            int k2n = (kt + 1) * 16;
            bh[0] = *(const uint4*)&g_w2h[brow * K2 + k2n + bkb];
            bh[1] = *(const uint4*)&g_w2h[brow * K2 + k2n + bkb + 4];
            bl[0] = *(const uint4*)&g_w2l[brow * K2 + k2n + bkb];
            bl[1] = *(const uint4*)&g_w2l[brow * K2 + k2n + bkb + 4];
        }

        #pragma unroll
        for (int ks = 0; ks < 2; ks++) {
            const uint32_t off = ks * 32;
            unsigned aH[2][4], aL[2][4], bHf[4][2], bLf[4][2];
            #pragma unroll
            for (int mt = 0; mt < 2; mt++) {
                LDSM_X4(aH[mt][0], aH[mt][1], aH[mt][2], aH[mt][3], aAH[mt] + off);
                LDSM_X4(aL[mt][0], aL[mt][1], aL[mt][2], aL[mt][3], aAL[mt] + off);
            }
            #pragma unroll
            for (int p = 0; p < 2; p++) {
                LDSM_X4(bHf[2*p][0], bHf[2*p][1], bHf[2*p+1][0], bHf[2*p+1][1], bAH[p] + off);
                LDSM_X4(bLf[2*p][0], bLf[2*p][1], bLf[2*p+1][0], bLf[2*p+1][1], bAL[p] + off);
            }
            #pragma unroll
            for (int mt = 0; mt < 2; mt++)
                #pragma unroll
                for (int nt = 0; nt < 4; nt++) {
                    MMA_F16(acc[mt][nt], aL[mt][0], aL[mt][1], aL[mt][2], aL[mt][3],
                            bHf[nt][0], bHf[nt][1]);
                    MMA_F16(acc[mt][nt], aH[mt][0], aH[mt][1], aH[mt][2], aH[mt][3],
                            bLf[nt][0], bLf[nt][1]);
                    MMA_F16(acc[mt][nt], aH[mt][0], aH[mt][1], aH[mt][2], aH[mt][3],
                            bHf[nt][0], bHf[nt][1]);
                }
        }
    }

    #pragma unroll
    for (int mt = 0; mt < 2; mt++) {
        int row0 = gm + wm + mt * 16 + (lane >> 2);
        int colb = (lane & 3) * 2;
        #pragma unroll
        for (int nt = 0; nt < 4; nt++) {
            int col = wn + nt * 8 + colb;
            *(float2*)&g_g2[(size_t)row0 * ND + col] =
                make_float2(acc[mt][nt][0], acc[mt][nt][1]);
            *(float2*)&g_g2[(size_t)(row0 + 8) * ND + col] =
                make_float2(acc[mt][nt][2], acc[mt][nt][3]);
        }
    }
}

// ---------------- sparse 3x3 neighbor sums ----------------
extern "C" __global__ __launch_bounds__(256)
void nsum1_kernel(const float* __restrict__ b1) {
    const int row = blockIdx.x * 8 + (threadIdx.x >> 5);
    const int lane = threadIdx.x & 31;
    const int b = row / KSEL, k = row - b * KSEL;
    const int i = g_sorted_idx[row];
    const int py = i / WW, px = i % WW;
    int nb = -1;
    if (lane < 9) {
        int ny = py + lane / 3 - 1, nx = px + lane % 3 - 1;
        if ((unsigned)ny < HH && (unsigned)nx < WW)
            nb = g_pos[b * HWSZ + ny * WW + nx];
    }
    float4 acc = *(const float4*)&b1[(size_t)k * ND + lane * 4];
    #pragma unroll
    for (int j = 0; j < 9; j++) {
        int n = __shfl_sync(0xFFFFFFFFu, nb, j);
        if (n >= 0) {
            float4 v = *(const float4*)&g_g1[(size_t)(b * KSEL + n) * ND + lane * 4];
            acc.x += v.x; acc.y += v.y; acc.z += v.z; acc.w += v.w;
        }
    }
    *(float4*)&g_x1[(size_t)row * ND + lane * 4] = acc;
}

extern "C" __global__ __launch_bounds__(256)
void final_kernel(const float* __restrict__ b2, float* __restrict__ out) {
    const int row = blockIdx.x * 8 + (threadIdx.x >> 5);
    const int lane = threadIdx.x & 31;
    const int b = row / KSEL, k = row - b * KSEL;
    const int i = g_sorted_idx[row];
    const int py = i / WW, px = i % WW;
    int nb = -1;
    if (lane < 9) {
        int ny = py + lane / 3 - 1, nx = px + lane % 3 - 1;
        if ((unsigned)ny < HH && (unsigned)nx < WW)
            nb = g_pos[b * HWSZ + ny * WW + nx];
    }
    float4 acc = *(const float4*)&b2[(size_t)k * ND + lane * 4];
    float4 x1v = *(const float4*)&g_x1[(size_t)row * ND + lane * 4];
    acc.x += x1v.x; acc.y += x1v.y; acc.z += x1v.z; acc.w += x1v.w;
    #pragma unroll
    for (int j = 0; j < 9; j++) {
        int n = __shfl_sync(0xFFFFFFFFu, nb, j);
        if (n >= 0) {
            float4 v = *(const float4*)&g_g2[(size_t)(b * KSEL + n) * ND + lane * 4];
            acc.x += v.x; acc.y += v.y; acc.z += v.z; acc.w += v.w;
        }
    }
    float4 o = make_float4(tanhf(acc.x), tanhf(acc.y), tanhf(acc.z), tanhf(acc.w));
    *(float4*)&out[(size_t)row * ND + lane * 4] = o;
}

// ---------------- launch ----------------
extern "C" void kernel_launch(void* const* d_in, const int* in_sizes, int n_in,
                              void* d_out, int out_size) {
    const float* feat = (const float*)d_in[0];
    const float* pred = (const float*)d_in[1];
    const float* w1   = (const float*)d_in[2];
    const float* b1   = (const float*)d_in[3];
    const float* w2   = (const float*)d_in[4];
    const float* b2   = (const float*)d_in[5];
    float* out = (float*)d_out;

    const int feat_elems = NROWS * ND;
    const int write_idx = (out_size >= feat_elems + NROWS) ? 1 : 0;

    cudaFuncSetAttribute((const void*)gather_kernel,
                         cudaFuncAttributeMaxDynamicSharedMemorySize, 60000);

    prep_kernel<<<(ND * (CH / 2) + ND * (ND / 2) + 255) / 256, 256>>>(w1, w2);
    topk_kernel<<<NB, 1024>>>(pred, out, write_idx);
    gather_kernel<<<NB * CPAIRS, 256, 60000>>>(feat);
    gemm1_kernel<<<NB * 32, 256>>>();
    nsum1_kernel<<<NROWS / 8, 256>>>(b1);
    gemm2_kernel<<<NROWS / 64, 256>>>();
    final_kernel<<<NROWS / 8, 256>>>(b2, out);
}